// round 10
// baseline (speedup 1.0000x reference)
#include <cuda_runtime.h>
#include <cuda_bf16.h>
#include <cstdint>

// ---------------- problem constants ----------------
#define NB    4
#define DIM   128
#define HEADS 8
#define PPTS  12544
#define CWID  112
#define WIN   7
#define NWX   16
#define WN    256
#define PT    49

// q,k,v: [n][h][win][tok=49][d=128], values pre-rounded to tf32
__device__ float g_q[(size_t)NB * HEADS * WN * PT * DIM];
__device__ float g_k[(size_t)NB * HEADS * WN * PT * DIM];
__device__ float g_v[(size_t)NB * HEADS * WN * PT * DIM];
__device__ float g_woF[(size_t)DIM * HEADS * DIM];        // Wo, fragment-major, tf32
__device__ float g_wR[(size_t)3 * HEADS * DIM * DIM];     // Wq/Wk/Wv rounded
__device__ float g_xR[(size_t)NB * DIM * PPTS];           // x rounded

__device__ __forceinline__ float tf32f(float x) {
    uint32_t u;
    asm("cvt.rna.tf32.f32 %0, %1;" : "=r"(u) : "f"(x));
    return __uint_as_float(u);
}

__device__ __forceinline__ void mma_tf32(float c[4], const uint32_t a[4], const uint32_t b[2]) {
    asm volatile(
        "mma.sync.aligned.m16n8k8.row.col.f32.tf32.tf32.f32 "
        "{%0,%1,%2,%3}, {%4,%5,%6,%7}, {%8,%9}, {%0,%1,%2,%3};\n"
        : "+f"(c[0]), "+f"(c[1]), "+f"(c[2]), "+f"(c[3])
        : "r"(a[0]), "r"(a[1]), "r"(a[2]), "r"(a[3]), "r"(b[0]), "r"(b[1]));
}

__device__ __forceinline__ void cp16(uint32_t smem_addr, const void* gptr) {
    asm volatile("cp.async.cg.shared.global [%0], [%1], 16;" :: "r"(smem_addr), "l"(gptr));
}
__device__ __forceinline__ void cp_commit() {
    asm volatile("cp.async.commit_group;");
}

// ---------------- prep kernels ----------------
__global__ void wo_frag_prep(const float* __restrict__ Wo) {
    int idx = blockIdx.x * 256 + threadIdx.x;       // 131072 total
    int lane = idx & 31;
    int ks   = (idx >> 5) & 15;
    int h    = (idx >> 9) & 7;
    int wd   = idx >> 12;                           // 0..7
    int g = lane >> 2, t = lane & 3;
    int row = wd * 16 + g;
    int col = h * 128 + ks * 8 + t;
    float4 v;
    v.x = tf32f(Wo[(size_t)row * 1024 + col]);
    v.y = tf32f(Wo[(size_t)(row + 8) * 1024 + col]);
    v.z = tf32f(Wo[(size_t)row * 1024 + col + 4]);
    v.w = tf32f(Wo[(size_t)(row + 8) * 1024 + col + 4]);
    ((float4*)g_woF)[idx] = v;
}
__global__ void w_prep(const float* __restrict__ Wq, const float* __restrict__ Wk,
                       const float* __restrict__ Wv) {
    int i = blockIdx.x * 256 + threadIdx.x;     // 32768 float4 per matrix
    const float* src = (blockIdx.y == 0) ? Wq : (blockIdx.y == 1) ? Wk : Wv;
    float4 v = ((const float4*)src)[i];
    ((float4*)g_wR)[(size_t)blockIdx.y * 32768 + i] =
        make_float4(tf32f(v.x), tf32f(v.y), tf32f(v.z), tf32f(v.w));
}
__global__ void x_prep(const float* __restrict__ x) {
    size_t i = (size_t)blockIdx.x * 256 + threadIdx.x;   // 1,605,632 float4
    float4 v = ((const float4*)x)[i];
    ((float4*)g_xR)[i] = make_float4(tf32f(v.x), tf32f(v.y), tf32f(v.z), tf32f(v.w));
}

// ---------------- Kernel A: persistent QKV projection ----------------
// 147 blocks x 256 threads; 64 tiles (M=128 o, N=128 p) per block.
// tiles: combo = which*32 + n*8 + h (96 combos), 98 p-tiles each; T = 9408.
// smem: As [128][132] @0 (66KB); per-warp B [2][32][40] @16896 (8*2560)
#define QA_OFF 0
#define QB_OFF 16896
#define Q_SM_FLOATS (16896 + 8 * 2 * 1280)   // 37376 floats = 149504 B

__global__ __launch_bounds__(256, 1)
void qkv_kernel(const float* __restrict__ bq, const float* __restrict__ bk,
                const float* __restrict__ bv) {
    extern __shared__ float qsm[];
    float* As = qsm + QA_OFF;                 // [o][k] stride 132

    int tid = threadIdx.x, lane = tid & 31, wid = tid >> 5;   // 8 warps
    int g = lane >> 2, t = lane & 3;
    int m0w = (wid >> 2) * 64, n0w = (wid & 3) * 32;

    float* Bw = qsm + QB_OFF + wid * 2560;    // [st][32][40] private
    uint32_t As_a = (uint32_t)__cvta_generic_to_shared(As);
    uint32_t Bw_a = (uint32_t)__cvta_generic_to_shared(Bw);

    int t0 = blockIdx.x * 64;
    int cbeg = t0 * 4, cend = cbeg + 256;     // 64 tiles * 4 chunks

    int cur_combo = -1;
    float* garr = g_q;
    const float* bvec = bq;
    size_t headbase = 0;
    float biasr[4][2] = {};
    float acc[4][4][4] = {};

    // prefetch B for first chunk
    {
        int tile = cbeg >> 2;
        int combo = tile / 98, pt = tile - combo * 98;
        int n = (combo >> 3) & 3;
        const float* xs = g_xR + (size_t)n * DIM * PPTS + pt * 128 + n0w;
        #pragma unroll
        for (int r = 0; r < 8; r++) {
            int idx = lane + r * 32;
            int kk = idx >> 3, c4 = idx & 7;
            cp16(Bw_a + (uint32_t)(kk * 40 + c4 * 4) * 4, xs + (size_t)kk * PPTS + c4 * 4);
        }
        cp_commit();
    }

    for (int ci = cbeg; ci < cend; ci++) {
        int tile = ci >> 2, kc = ci & 3, st = ci & 1;
        int combo = tile / 98;
        int pt = tile - combo * 98;
        int p_base = pt * 128;

        bool nc = (kc == 0) && (combo != cur_combo);
        if (nc) {
            __syncthreads();                  // all warps done with old A
            int which = combo >> 5;
            int n = (combo >> 3) & 3;
            int h = combo & 7;
            const float* Wsrc = g_wR + (size_t)which * 131072 + (size_t)h * 16384;
            #pragma unroll
            for (int r = 0; r < 16; r++) {
                int i = tid + r * 256;
                int row = i >> 5, c = i & 31;
                cp16(As_a + (uint32_t)(row * 132 + c * 4) * 4, Wsrc + (size_t)row * 128 + c * 4);
            }
            cp_commit();
            garr = (which == 0) ? g_q : (which == 1) ? g_k : g_v;
            bvec = (which == 0) ? bq : (which == 1) ? bk : bv;
            headbase = ((size_t)n * HEADS + h) * WN;
            #pragma unroll
            for (int mf = 0; mf < 4; mf++)
                #pragma unroll
                for (int rs = 0; rs < 2; rs++)
                    biasr[mf][rs] = bvec[h * 128 + m0w + mf * 16 + rs * 8 + g];
            cur_combo = combo;
        }

        // prefetch next chunk's B (per-warp)
        if (ci + 1 < cend) {
            int tile2 = (ci + 1) >> 2, kc2 = (ci + 1) & 3, st2 = (ci + 1) & 1;
            int combo2 = tile2 / 98, pt2 = tile2 - combo2 * 98;
            int n2 = (combo2 >> 3) & 3;
            const float* xs = g_xR + (size_t)n2 * DIM * PPTS
                            + (size_t)(kc2 * 32) * PPTS + pt2 * 128 + n0w;
            uint32_t dst = Bw_a + (uint32_t)(st2 * 1280) * 4;
            #pragma unroll
            for (int r = 0; r < 8; r++) {
                int idx = lane + r * 32;
                int kk = idx >> 3, c4 = idx & 7;
                cp16(dst + (uint32_t)(kk * 40 + c4 * 4) * 4, xs + (size_t)kk * PPTS + c4 * 4);
            }
            cp_commit();
            asm volatile("cp.async.wait_group 1;");
        } else {
            asm volatile("cp.async.wait_group 0;");
        }
        if (nc) __syncthreads();              // A visible to all warps

        // ---- mma on chunk (A cols kc*32..+32, private B buffer st) ----
        const float* Bst = Bw + st * 1280;
        int acol = kc * 32;
        #pragma unroll
        for (int ks = 0; ks < 4; ks++) {
            int k0 = ks * 8;
            uint32_t af[4][4], bf[4][2];
            #pragma unroll
            for (int mf = 0; mf < 4; mf++) {
                int m = m0w + mf * 16;
                af[mf][0] = __float_as_uint(As[(m + g) * 132 + acol + k0 + t]);
                af[mf][1] = __float_as_uint(As[(m + g + 8) * 132 + acol + k0 + t]);
                af[mf][2] = __float_as_uint(As[(m + g) * 132 + acol + k0 + t + 4]);
                af[mf][3] = __float_as_uint(As[(m + g + 8) * 132 + acol + k0 + t + 4]);
            }
            #pragma unroll
            for (int nf = 0; nf < 4; nf++) {
                bf[nf][0] = __float_as_uint(Bst[(k0 + t) * 40 + nf * 8 + g]);
                bf[nf][1] = __float_as_uint(Bst[(k0 + t + 4) * 40 + nf * 8 + g]);
            }
            #pragma unroll
            for (int mf = 0; mf < 4; mf++)
                #pragma unroll
                for (int nf = 0; nf < 4; nf++)
                    mma_tf32(acc[mf][nf], af[mf], bf[nf]);
        }

        // ---- epilogue at end of each tile (warp-local, no barrier) ----
        if (kc == 3) {
            #pragma unroll
            for (int nf = 0; nf < 4; nf++) {
                #pragma unroll
                for (int cs = 0; cs < 2; cs++) {
                    int p = p_base + n0w + nf * 8 + 2 * t + cs;
                    int pr = p / CWID, pc = p - pr * CWID;
                    int win = (pr / WIN) * NWX + (pc / WIN);
                    int tok = (pr % WIN) * WIN + (pc % WIN);
                    float* base = garr + ((headbase + win) * PT + tok) * DIM;
                    #pragma unroll
                    for (int mf = 0; mf < 4; mf++)
                        #pragma unroll
                        for (int rs = 0; rs < 2; rs++) {
                            int d = m0w + mf * 16 + rs * 8 + g;
                            base[d] = tf32f(acc[mf][nf][rs * 2 + cs] + biasr[mf][rs]);
                        }
                }
            }
            #pragma unroll
            for (int mf = 0; mf < 4; mf++)
                #pragma unroll
                for (int nf = 0; nf < 4; nf++)
                    #pragma unroll
                    for (int r = 0; r < 4; r++)
                        acc[mf][nf][r] = 0.f;
        }
    }
}

// ---------------- Kernel B: fused attention + output projection ----------------
#define SQ_OFF  0          // sq/att [64][132]  (aliased)
#define SK_OFF  8448       // sk  [56][132]
#define SV_OFF  15840      // sv  [56][132] (rows 49..55 zeroed once)
#define SS_OFF  23232      // S   [64][60]
#define SB_OFF  27072      // sball [8][176]
#define SM_FLOATS 28480    // 113,920 B

__global__ __launch_bounds__(256, 2)
void attn_out_kernel(const float* __restrict__ pos_code,
                     const float* __restrict__ bo,
                     float* __restrict__ out) {
    extern __shared__ float sm[];
    float* sq    = sm + SQ_OFF;
    float* sk    = sm + SK_OFF;
    float* sv    = sm + SV_OFF;
    float* att   = sm + SQ_OFF;       // alias: q dead after QK
    float* S     = sm + SS_OFF;
    float* sball = sm + SB_OFF;

    int bid = blockIdx.x;
    int w = bid & 255;
    int n = bid >> 8;
    int tid = threadIdx.x, lane = tid & 31, wid = tid >> 5;
    int g = lane >> 2, t = lane & 3;
    int m0 = (wid >> 1) * 16;
    int half = wid & 1;
    int om0 = wid * 16;

    uint32_t sq_a = (uint32_t)__cvta_generic_to_shared(sq);
    uint32_t sk_a = (uint32_t)__cvta_generic_to_shared(sk);
    uint32_t sv_a = (uint32_t)__cvta_generic_to_shared(sv);

    size_t winbase = ((size_t)n * HEADS) * WN + w;

    for (int i = tid; i < 7 * 132; i += 256) sv[49 * 132 + i] = 0.f;
    for (int j = tid; j < 169 * HEADS; j += 256) {
        int hh = j & 7, ii = j >> 3;
        sball[hh * 176 + ii] = pos_code[j];
    }

    {
        const float4* gq4 = (const float4*)(g_q + winbase * (PT * DIM));
        const float4* gk4 = (const float4*)(g_k + winbase * (PT * DIM));
        const float4* gv4 = (const float4*)(g_v + winbase * (PT * DIM));
        for (int i = tid; i < PT * 32; i += 256) {
            int r = i >> 5, c = i & 31;
            uint32_t off = (uint32_t)(r * 132 + c * 4) * 4;
            cp16(sq_a + off, gq4 + i);
            cp16(sk_a + off, gk4 + i);
            cp16(sv_a + off, gv4 + i);
        }
        cp_commit();
    }

    float acc_o[7][4] = {};
    const float scale = 0.08838834764831845f;

    for (int h = 0; h < 8; h++) {
        asm volatile("cp.async.wait_group 0;");
        __syncthreads();

        const float* sb = sball + h * 176;
        size_t nextbase = winbase + (size_t)(h + 1) * WN;

        // ---- QK ----
        {
            float acc[4][4] = {};
            #pragma unroll
            for (int ks = 0; ks < 16; ks++) {
                int k0 = ks * 8;
                uint32_t a[4];
                a[0] = __float_as_uint(sq[(m0 + g) * 132 + k0 + t]);
                a[1] = __float_as_uint(sq[(m0 + g + 8) * 132 + k0 + t]);
                a[2] = __float_as_uint(sq[(m0 + g) * 132 + k0 + t + 4]);
                a[3] = __float_as_uint(sq[(m0 + g + 8) * 132 + k0 + t + 4]);
                #pragma unroll
                for (int nt = 0; nt < 4; nt++) {
                    int nti = half * 4 + nt;
                    if (nti >= 7) break;
                    int n0 = nti * 8;
                    uint32_t b[2];
                    b[0] = __float_as_uint(sk[(n0 + g) * 132 + k0 + t]);
                    b[1] = __float_as_uint(sk[(n0 + g) * 132 + k0 + t + 4]);
                    mma_tf32(acc[nt], a, b);
                }
            }
            #pragma unroll
            for (int nt = 0; nt < 4; nt++) {
                int nti = half * 4 + nt;
                if (nti >= 7) break;
                int n0 = nti * 8;
                S[(m0 + g) * 60 + n0 + 2 * t]     = acc[nt][0];
                S[(m0 + g) * 60 + n0 + 2 * t + 1] = acc[nt][1];
                S[(m0 + g + 8) * 60 + n0 + 2 * t]     = acc[nt][2];
                S[(m0 + g + 8) * 60 + n0 + 2 * t + 1] = acc[nt][3];
            }
        }
        __syncthreads();

        if (h < 7) {
            const float4* gk4 = (const float4*)(g_k + nextbase * (PT * DIM));
            for (int i = tid; i < PT * 32; i += 256) {
                int r = i >> 5, c = i & 31;
                cp16(sk_a + (uint32_t)(r * 132 + c * 4) * 4, gk4 + i);
            }
            cp_commit();
        }

        // ---- softmax ----
        for (int j = wid; j < PT; j += 8) {
            int yj = j / WIN, xj = j - yj * WIN;
            float* row = S + j * 60;
            int i0 = lane;
            int y0 = i0 / WIN, x0 = i0 - y0 * WIN;
            int r0 = (y0 - yj + WIN - 1) + (x0 - xj + WIN - 1) * (2 * WIN - 1);
            float v0 = row[i0] * scale + sb[r0];
            float v1 = -1e30f;
            int i1 = lane + 32;
            if (i1 < PT) {
                int y1 = i1 / WIN, x1 = i1 - y1 * WIN;
                int r1 = (y1 - yj + WIN - 1) + (x1 - xj + WIN - 1) * (2 * WIN - 1);
                v1 = row[i1] * scale + sb[r1];
            }
            float m = fmaxf(v0, v1);
            #pragma unroll
            for (int off = 16; off; off >>= 1) m = fmaxf(m, __shfl_xor_sync(0xffffffffu, m, off));
            float e0 = __expf(v0 - m);
            float e1 = (i1 < PT) ? __expf(v1 - m) : 0.f;
            float s = e0 + e1;
            #pragma unroll
            for (int off = 16; off; off >>= 1) s += __shfl_xor_sync(0xffffffffu, s, off);
            float inv = 1.f / s;
            row[i0] = tf32f(e0 * inv);
            if (i1 < PT) row[i1] = tf32f(e1 * inv);
            else if (i1 < 56) row[i1] = 0.f;
        }
        __syncthreads();

        // ---- PV ----
        {
            float acc[8][4] = {};
            #pragma unroll
            for (int ks = 0; ks < 7; ks++) {
                int k0 = ks * 8;
                uint32_t a[4];
                a[0] = __float_as_uint(S[(m0 + g) * 60 + k0 + t]);
                a[1] = __float_as_uint(S[(m0 + g + 8) * 60 + k0 + t]);
                a[2] = __float_as_uint(S[(m0 + g) * 60 + k0 + t + 4]);
                a[3] = __float_as_uint(S[(m0 + g + 8) * 60 + k0 + t + 4]);
                #pragma unroll
                for (int nt = 0; nt < 8; nt++) {
                    int n0 = (half * 8 + nt) * 8;
                    uint32_t b[2];
                    b[0] = __float_as_uint(sv[(k0 + t) * 132 + n0 + g]);
                    b[1] = __float_as_uint(sv[(k0 + t + 4) * 132 + n0 + g]);
                    mma_tf32(acc[nt], a, b);
                }
            }
            #pragma unroll
            for (int nt = 0; nt < 8; nt++) {
                int d0 = (half * 8 + nt) * 8 + 2 * t;
                att[(m0 + g) * 132 + d0]         = tf32f(acc[nt][0]);
                att[(m0 + g) * 132 + d0 + 1]     = tf32f(acc[nt][1]);
                att[(m0 + g + 8) * 132 + d0]     = tf32f(acc[nt][2]);
                att[(m0 + g + 8) * 132 + d0 + 1] = tf32f(acc[nt][3]);
            }
        }
        __syncthreads();

        if (h < 7) {
            const float4* gv4 = (const float4*)(g_v + nextbase * (PT * DIM));
            for (int i = tid; i < PT * 32; i += 256) {
                int r = i >> 5, c = i & 31;
                cp16(sv_a + (uint32_t)(r * 132 + c * 4) * 4, gv4 + i);
            }
            cp_commit();
        }

        // ---- out accumulate: Wo fragments via one LDG.128 per ks ----
        {
            const float4* wof = ((const float4*)g_woF) + ((size_t)(wid * 8 + h) * 16) * 32 + lane;
            #pragma unroll
            for (int ks = 0; ks < 16; ks++) {
                int k0 = ks * 8;
                float4 av = __ldg(wof + ks * 32);
                uint32_t a[4] = {__float_as_uint(av.x), __float_as_uint(av.y),
                                 __float_as_uint(av.z), __float_as_uint(av.w)};
                #pragma unroll
                for (int nt = 0; nt < 7; nt++) {
                    uint32_t b[2];
                    b[0] = __float_as_uint(att[(nt * 8 + g) * 132 + k0 + t]);
                    b[1] = __float_as_uint(att[(nt * 8 + g) * 132 + k0 + t + 4]);
                    mma_tf32(acc_o[nt], a, b);
                }
            }
        }
        __syncthreads();

        if (h < 7) {
            const float4* gq4 = (const float4*)(g_q + nextbase * (PT * DIM));
            for (int i = tid; i < PT * 32; i += 256) {
                int r = i >> 5, c = i & 31;
                cp16(sq_a + (uint32_t)(r * 132 + c * 4) * 4, gq4 + i);
            }
            cp_commit();
        }
    }

    // ---- final store ----
    int wy = w >> 4, wx = w & 15;
    float* dst_n = out + (size_t)n * DIM * PPTS;
    #pragma unroll
    for (int rs = 0; rs < 2; rs++) {
        int o = om0 + g + rs * 8;
        float bias = bo[o];
        float* dst = dst_n + (size_t)o * PPTS;
        #pragma unroll
        for (int nt = 0; nt < 7; nt++) {
            #pragma unroll
            for (int cs = 0; cs < 2; cs++) {
                int tok = nt * 8 + 2 * t + cs;
                if (tok < PT) {
                    int jy = tok / WIN, jx = tok - jy * WIN;
                    int p = (wy * WIN + jy) * CWID + wx * WIN + jx;
                    dst[p] = acc_o[nt][rs * 2 + cs] + bias;
                }
            }
        }
    }
}

// ---------------- launch ----------------
extern "C" void kernel_launch(void* const* d_in, const int* in_sizes, int n_in,
                              void* d_out, int out_size) {
    const float* x   = (const float*)d_in[0];
    const float* Wq  = (const float*)d_in[1];
    const float* bq  = (const float*)d_in[2];
    const float* Wk  = (const float*)d_in[3];
    const float* bk  = (const float*)d_in[4];
    const float* Wv  = (const float*)d_in[5];
    const float* bv  = (const float*)d_in[6];
    const float* Wo  = (const float*)d_in[7];
    const float* bo  = (const float*)d_in[8];
    const float* pos = (const float*)d_in[9];
    float* out = (float*)d_out;

    wo_frag_prep<<<512, 256>>>(Wo);
    {
        dim3 gw(128, 3);
        w_prep<<<gw, 256>>>(Wq, Wk, Wv);
    }
    x_prep<<<6272, 256>>>(x);

    {
        static int attr_set = 0;
        if (!attr_set) {
            cudaFuncSetAttribute(qkv_kernel, cudaFuncAttributeMaxDynamicSharedMemorySize,
                                 Q_SM_FLOATS * (int)sizeof(float));
            cudaFuncSetAttribute(attn_out_kernel, cudaFuncAttributeMaxDynamicSharedMemorySize,
                                 SM_FLOATS * (int)sizeof(float));
            attr_set = 1;
        }
    }
    qkv_kernel<<<147, 256, Q_SM_FLOATS * sizeof(float)>>>(bq, bk, bv);
    attn_out_kernel<<<NB * WN, 256, SM_FLOATS * sizeof(float)>>>(pos, bo, out);
}

// round 12
// speedup vs baseline: 1.1435x; 1.1435x over previous
#include <cuda_runtime.h>
#include <cuda_bf16.h>
#include <cstdint>

// ---------------- problem constants ----------------
#define NB    4
#define DIM   128
#define HEADS 8
#define PPTS  12544
#define CWID  112
#define WIN   7
#define NWX   16
#define WN    256
#define PT    49

// q,k,v: [n][h][win][tok=49][d=128], values pre-rounded to tf32
__device__ float g_q[(size_t)NB * HEADS * WN * PT * DIM];
__device__ float g_k[(size_t)NB * HEADS * WN * PT * DIM];
__device__ float g_v[(size_t)NB * HEADS * WN * PT * DIM];
__device__ float g_woF[(size_t)DIM * HEADS * DIM];        // Wo, fragment-major, tf32
__device__ float g_wR[(size_t)3 * HEADS * DIM * DIM];     // Wq/Wk/Wv rounded
__device__ float g_xR[(size_t)NB * DIM * PPTS];           // x rounded

__device__ __forceinline__ float tf32f(float x) {
    uint32_t u;
    asm("cvt.rna.tf32.f32 %0, %1;" : "=r"(u) : "f"(x));
    return __uint_as_float(u);
}

__device__ __forceinline__ void mma_tf32(float c[4], const uint32_t a[4], const uint32_t b[2]) {
    asm volatile(
        "mma.sync.aligned.m16n8k8.row.col.f32.tf32.tf32.f32 "
        "{%0,%1,%2,%3}, {%4,%5,%6,%7}, {%8,%9}, {%0,%1,%2,%3};\n"
        : "+f"(c[0]), "+f"(c[1]), "+f"(c[2]), "+f"(c[3])
        : "r"(a[0]), "r"(a[1]), "r"(a[2]), "r"(a[3]), "r"(b[0]), "r"(b[1]));
}

__device__ __forceinline__ void cp16(uint32_t smem_addr, const void* gptr) {
    asm volatile("cp.async.cg.shared.global [%0], [%1], 16;" :: "r"(smem_addr), "l"(gptr));
}
__device__ __forceinline__ void cp_commit() {
    asm volatile("cp.async.commit_group;");
}

// ---------------- prep kernels ----------------
__global__ void wo_frag_prep(const float* __restrict__ Wo) {
    int idx = blockIdx.x * 256 + threadIdx.x;       // 131072 total
    int lane = idx & 31;
    int ks   = (idx >> 5) & 15;
    int h    = (idx >> 9) & 7;
    int wd   = idx >> 12;                           // 0..7
    int g = lane >> 2, t = lane & 3;
    int row = wd * 16 + g;
    int col = h * 128 + ks * 8 + t;
    float4 v;
    v.x = tf32f(Wo[(size_t)row * 1024 + col]);
    v.y = tf32f(Wo[(size_t)(row + 8) * 1024 + col]);
    v.z = tf32f(Wo[(size_t)row * 1024 + col + 4]);
    v.w = tf32f(Wo[(size_t)(row + 8) * 1024 + col + 4]);
    ((float4*)g_woF)[idx] = v;
}
__global__ void w_prep(const float* __restrict__ Wq, const float* __restrict__ Wk,
                       const float* __restrict__ Wv) {
    int i = blockIdx.x * 256 + threadIdx.x;     // 32768 float4 per matrix
    const float* src = (blockIdx.y == 0) ? Wq : (blockIdx.y == 1) ? Wk : Wv;
    float4 v = ((const float4*)src)[i];
    ((float4*)g_wR)[(size_t)blockIdx.y * 32768 + i] =
        make_float4(tf32f(v.x), tf32f(v.y), tf32f(v.z), tf32f(v.w));
}
__global__ void x_prep(const float* __restrict__ x) {
    size_t i = (size_t)blockIdx.x * 256 + threadIdx.x;   // 1,605,632 float4
    float4 v = ((const float4*)x)[i];
    ((float4*)g_xR)[i] = make_float4(tf32f(v.x), tf32f(v.y), tf32f(v.z), tf32f(v.w));
}

// ---------------- Kernel A: QKV projection, 2 p-tiles per block (R9) ----------------
#define QA_OFF 0
#define QB_OFF 16896
#define Q_SM_FLOATS 25600

__global__ __launch_bounds__(128, 2)
void qkv_kernel(const float* __restrict__ bq, const float* __restrict__ bk,
                const float* __restrict__ bv) {
    extern __shared__ float qsm[];
    float* As = qsm + QA_OFF;                 // [o][k] stride 132
    float* Bs = qsm + QB_OFF;                 // [st][k][p] stride 136

    int z = blockIdx.z;
    int n = z & 3;
    int which = z >> 2;
    const float* bvec = (which == 0) ? bq : (which == 1) ? bk : bv;
    float* garr = (which == 0) ? g_q : (which == 1) ? g_k : g_v;
    int h = blockIdx.y;
    int p_base = blockIdx.x * 256;            // two 128-wide p tiles
    const float* Wsrc = g_wR + (size_t)which * 131072 + (size_t)h * 128 * 128;
    const float* xn = g_xR + (size_t)n * DIM * PPTS;

    int tid = threadIdx.x, lane = tid & 31, wid = tid >> 5;   // 4 warps
    int g = lane >> 2, t = lane & 3;
    int m0w = (wid >> 1) * 64, n0w = (wid & 1) * 64;

    uint32_t As_a = (uint32_t)__cvta_generic_to_shared(As);
    uint32_t Bs_a = (uint32_t)__cvta_generic_to_shared(Bs);

    #pragma unroll
    for (int r = 0; r < 32; r++) {
        int i = tid + r * 128;
        int row = i >> 5, c = i & 31;
        cp16(As_a + (uint32_t)(row * 132 + c * 4) * 4, Wsrc + (size_t)row * 128 + c * 4);
    }
    #pragma unroll
    for (int r = 0; r < 8; r++) {
        int i = tid + r * 128;
        int kk = i >> 5, c = i & 31;
        cp16(Bs_a + (uint32_t)(kk * 136 + c * 4) * 4, xn + (size_t)kk * PPTS + p_base + c * 4);
    }
    cp_commit();

    float acc[4][8][4] = {};
    size_t headbase = ((size_t)n * HEADS + h) * WN;
    float biasr[4][2];
    #pragma unroll
    for (int mf = 0; mf < 4; mf++)
        #pragma unroll
        for (int rs = 0; rs < 2; rs++)
            biasr[mf][rs] = bvec[h * 128 + m0w + mf * 16 + rs * 8 + g];

    #pragma unroll
    for (int c = 0; c < 8; c++) {
        int st = c & 1;
        if (c < 7) {
            int nst = (c + 1) & 1;
            int k0n = ((c + 1) & 3) * 32;
            int pbn = p_base + ((c + 1) >> 2) * 128;
            #pragma unroll
            for (int r = 0; r < 8; r++) {
                int i = tid + r * 128;
                int kk = i >> 5, cc = i & 31;
                cp16(Bs_a + (uint32_t)(nst * 32 * 136 + kk * 136 + cc * 4) * 4,
                     xn + (size_t)(k0n + kk) * PPTS + pbn + cc * 4);
            }
            cp_commit();
            asm volatile("cp.async.wait_group 1;");
        } else {
            asm volatile("cp.async.wait_group 0;");
        }
        __syncthreads();

        const float* Bst = Bs + st * (32 * 136);
        int acol = (c & 3) * 32;
        #pragma unroll
        for (int ks = 0; ks < 4; ks++) {
            int k0 = ks * 8;
            uint32_t af[4][4], bf[8][2];
            #pragma unroll
            for (int mf = 0; mf < 4; mf++) {
                int m = m0w + mf * 16;
                af[mf][0] = __float_as_uint(As[(m + g) * 132 + acol + k0 + t]);
                af[mf][1] = __float_as_uint(As[(m + g + 8) * 132 + acol + k0 + t]);
                af[mf][2] = __float_as_uint(As[(m + g) * 132 + acol + k0 + t + 4]);
                af[mf][3] = __float_as_uint(As[(m + g + 8) * 132 + acol + k0 + t + 4]);
            }
            #pragma unroll
            for (int nf = 0; nf < 8; nf++) {
                int nn = n0w + nf * 8 + g;
                bf[nf][0] = __float_as_uint(Bst[(k0 + t) * 136 + nn]);
                bf[nf][1] = __float_as_uint(Bst[(k0 + t + 4) * 136 + nn]);
            }
            #pragma unroll
            for (int mf = 0; mf < 4; mf++)
                #pragma unroll
                for (int nf = 0; nf < 8; nf++)
                    mma_tf32(acc[mf][nf], af[mf], bf[nf]);
        }
        __syncthreads();

        if ((c & 3) == 3) {
            int pb = p_base + (c >> 2) * 128;
            #pragma unroll
            for (int nf = 0; nf < 8; nf++) {
                #pragma unroll
                for (int cs = 0; cs < 2; cs++) {
                    int p = pb + n0w + nf * 8 + 2 * t + cs;
                    int pr = p / CWID, pc = p - pr * CWID;
                    int win = (pr / WIN) * NWX + (pc / WIN);
                    int tok = (pr % WIN) * WIN + (pc % WIN);
                    float* base = garr + ((headbase + win) * PT + tok) * DIM;
                    #pragma unroll
                    for (int mf = 0; mf < 4; mf++)
                        #pragma unroll
                        for (int rs = 0; rs < 2; rs++) {
                            int d = m0w + mf * 16 + rs * 8 + g;
                            base[d] = tf32f(acc[mf][nf][rs * 2 + cs] + biasr[mf][rs]);
                        }
                }
            }
            if (c == 3) {
                #pragma unroll
                for (int mf = 0; mf < 4; mf++)
                    #pragma unroll
                    for (int nf = 0; nf < 8; nf++)
                        #pragma unroll
                        for (int r = 0; r < 4; r++)
                            acc[mf][nf][r] = 0.f;
            }
        }
    }
}

// ---------------- Kernel B: fused attention + output projection ----------------
// QK+softmax fused: warps 0-3 own full S rows; register softmax via quad shfl.
#define SQ_OFF  0          // sq/att [64][132]  (aliased)
#define SK_OFF  8448       // sk  [56][132]
#define SV_OFF  15840      // sv  [56][132] (rows 49..55 zeroed once)
#define SS_OFF  23232      // S   [64][60]  (P matrix)
#define SB_OFF  27072      // sball [8][176]
#define SM_FLOATS 28480    // 113,920 B

__global__ __launch_bounds__(256, 2)
void attn_out_kernel(const float* __restrict__ pos_code,
                     const float* __restrict__ bo,
                     float* __restrict__ out) {
    extern __shared__ float sm[];
    float* sq    = sm + SQ_OFF;
    float* sk    = sm + SK_OFF;
    float* sv    = sm + SV_OFF;
    float* att   = sm + SQ_OFF;       // alias: q dead after QK
    float* S     = sm + SS_OFF;
    float* sball = sm + SB_OFF;

    int bid = blockIdx.x;
    int w = bid & 255;
    int n = bid >> 8;
    int tid = threadIdx.x, lane = tid & 31, wid = tid >> 5;
    int g = lane >> 2, t = lane & 3;
    int m0 = (wid >> 1) * 16;         // PV j-tile (8 warps)
    int half = wid & 1;
    int om0 = wid * 16;               // out o-tile

    uint32_t sq_a = (uint32_t)__cvta_generic_to_shared(sq);
    uint32_t sk_a = (uint32_t)__cvta_generic_to_shared(sk);
    uint32_t sv_a = (uint32_t)__cvta_generic_to_shared(sv);

    size_t winbase = ((size_t)n * HEADS) * WN + w;

    for (int i = tid; i < 7 * 132; i += 256) sv[49 * 132 + i] = 0.f;
    for (int j = tid; j < 169 * HEADS; j += 256) {
        int hh = j & 7, ii = j >> 3;
        sball[hh * 176 + ii] = pos_code[j];
    }

    // static per-thread i-mapping for QK softmax (warps 0-3 path)
    int ib[14];           // base_i = yi + 13*xi, or -1 for pad cols
    #pragma unroll
    for (int nt = 0; nt < 7; nt++) {
        #pragma unroll
        for (int cs = 0; cs < 2; cs++) {
            int i = nt * 8 + 2 * t + cs;
            int yi = i / WIN, xi = i - yi * WIN;
            ib[nt * 2 + cs] = (i < PT) ? (yi + 13 * xi) : -1;
        }
    }
    // row bias offsets (QK warps): rows j1 = wid*16+g, j2 = +8
    int qj1 = wid * 16 + g, qj2 = qj1 + 8;
    int off1, off2;
    {
        int y1 = qj1 / WIN, x1 = qj1 - y1 * WIN;
        int y2 = qj2 / WIN, x2 = qj2 - y2 * WIN;
        off1 = (WIN - 1 - y1) + 13 * (WIN - 1 - x1);
        off2 = (WIN - 1 - y2) + 13 * (WIN - 1 - x2);
    }

    {
        const float4* gq4 = (const float4*)(g_q + winbase * (PT * DIM));
        const float4* gk4 = (const float4*)(g_k + winbase * (PT * DIM));
        const float4* gv4 = (const float4*)(g_v + winbase * (PT * DIM));
        for (int i = tid; i < PT * 32; i += 256) {
            int r = i >> 5, c = i & 31;
            uint32_t off = (uint32_t)(r * 132 + c * 4) * 4;
            cp16(sq_a + off, gq4 + i);
            cp16(sk_a + off, gk4 + i);
            cp16(sv_a + off, gv4 + i);
        }
        cp_commit();
    }

    float acc_o[7][4] = {};
    const float scale = 0.08838834764831845f;

    for (int h = 0; h < 8; h++) {
        asm volatile("cp.async.wait_group 0;");
        __syncthreads();

        const float* sb = sball + h * 176;
        size_t nextbase = winbase + (size_t)(h + 1) * WN;

        // ---- fused QK + softmax: warps 0-3, each owns 16 full rows ----
        if (wid < 4) {
            float acc[7][4] = {};
            #pragma unroll
            for (int ks = 0; ks < 16; ks++) {
                int k0 = ks * 8;
                uint32_t a[4];
                a[0] = __float_as_uint(sq[qj1 * 132 + k0 + t]);
                a[1] = __float_as_uint(sq[qj2 * 132 + k0 + t]);
                a[2] = __float_as_uint(sq[qj1 * 132 + k0 + t + 4]);
                a[3] = __float_as_uint(sq[qj2 * 132 + k0 + t + 4]);
                #pragma unroll
                for (int nt = 0; nt < 7; nt++) {
                    int n0 = nt * 8;
                    uint32_t b[2];
                    b[0] = __float_as_uint(sk[(n0 + g) * 132 + k0 + t]);
                    b[1] = __float_as_uint(sk[(n0 + g) * 132 + k0 + t + 4]);
                    mma_tf32(acc[nt], a, b);
                }
            }
            // scale + bias, pad -> -inf
            #pragma unroll
            for (int nt = 0; nt < 7; nt++) {
                #pragma unroll
                for (int cs = 0; cs < 2; cs++) {
                    int bi = ib[nt * 2 + cs];
                    if (bi >= 0) {
                        acc[nt][cs]     = acc[nt][cs]     * scale + sb[bi + off1];
                        acc[nt][2 + cs] = acc[nt][2 + cs] * scale + sb[bi + off2];
                    } else {
                        acc[nt][cs] = -1e30f;
                        acc[nt][2 + cs] = -1e30f;
                    }
                }
            }
            // row max (quad reduce over t)
            float m1 = -1e30f, m2 = -1e30f;
            #pragma unroll
            for (int k = 0; k < 7; k++) {
                m1 = fmaxf(m1, fmaxf(acc[k][0], acc[k][1]));
                m2 = fmaxf(m2, fmaxf(acc[k][2], acc[k][3]));
            }
            m1 = fmaxf(m1, __shfl_xor_sync(0xffffffffu, m1, 1));
            m1 = fmaxf(m1, __shfl_xor_sync(0xffffffffu, m1, 2));
            m2 = fmaxf(m2, __shfl_xor_sync(0xffffffffu, m2, 1));
            m2 = fmaxf(m2, __shfl_xor_sync(0xffffffffu, m2, 2));
            // exp + sum
            float s1 = 0.f, s2 = 0.f;
            #pragma unroll
            for (int k = 0; k < 7; k++) {
                acc[k][0] = __expf(acc[k][0] - m1); s1 += acc[k][0];
                acc[k][1] = __expf(acc[k][1] - m1); s1 += acc[k][1];
                acc[k][2] = __expf(acc[k][2] - m2); s2 += acc[k][2];
                acc[k][3] = __expf(acc[k][3] - m2); s2 += acc[k][3];
            }
            s1 += __shfl_xor_sync(0xffffffffu, s1, 1);
            s1 += __shfl_xor_sync(0xffffffffu, s1, 2);
            s2 += __shfl_xor_sync(0xffffffffu, s2, 1);
            s2 += __shfl_xor_sync(0xffffffffu, s2, 2);
            float inv1 = 1.f / s1, inv2 = 1.f / s2;
            // store normalized P (tf32), pad cols get exp(-inf)=0
            #pragma unroll
            for (int nt = 0; nt < 7; nt++) {
                int n0 = nt * 8;
                S[qj1 * 60 + n0 + 2 * t]     = tf32f(acc[nt][0] * inv1);
                S[qj1 * 60 + n0 + 2 * t + 1] = tf32f(acc[nt][1] * inv1);
                S[qj2 * 60 + n0 + 2 * t]     = tf32f(acc[nt][2] * inv2);
                S[qj2 * 60 + n0 + 2 * t + 1] = tf32f(acc[nt][3] * inv2);
            }
        }
        __syncthreads();

        // prefetch next k (sk free after QK)
        if (h < 7) {
            const float4* gk4 = (const float4*)(g_k + nextbase * (PT * DIM));
            for (int i = tid; i < PT * 32; i += 256) {
                int r = i >> 5, c = i & 31;
                cp16(sk_a + (uint32_t)(r * 132 + c * 4) * 4, gk4 + i);
            }
            cp_commit();
        }

        // ---- PV: att[j][d] = P @ V; m=64(j), n=128(d), k=56; 8 warps ----
        {
            float acc[8][4] = {};
            #pragma unroll
            for (int ks = 0; ks < 7; ks++) {
                int k0 = ks * 8;
                uint32_t a[4];
                a[0] = __float_as_uint(S[(m0 + g) * 60 + k0 + t]);
                a[1] = __float_as_uint(S[(m0 + g + 8) * 60 + k0 + t]);
                a[2] = __float_as_uint(S[(m0 + g) * 60 + k0 + t + 4]);
                a[3] = __float_as_uint(S[(m0 + g + 8) * 60 + k0 + t + 4]);
                #pragma unroll
                for (int nt = 0; nt < 8; nt++) {
                    int n0 = (half * 8 + nt) * 8;
                    uint32_t b[2];
                    b[0] = __float_as_uint(sv[(k0 + t) * 132 + n0 + g]);
                    b[1] = __float_as_uint(sv[(k0 + t + 4) * 132 + n0 + g]);
                    mma_tf32(acc[nt], a, b);
                }
            }
            #pragma unroll
            for (int nt = 0; nt < 8; nt++) {
                int d0 = (half * 8 + nt) * 8 + 2 * t;
                att[(m0 + g) * 132 + d0]         = tf32f(acc[nt][0]);
                att[(m0 + g) * 132 + d0 + 1]     = tf32f(acc[nt][1]);
                att[(m0 + g + 8) * 132 + d0]     = tf32f(acc[nt][2]);
                att[(m0 + g + 8) * 132 + d0 + 1] = tf32f(acc[nt][3]);
            }
        }
        __syncthreads();

        // prefetch next v (sv free after PV)
        if (h < 7) {
            const float4* gv4 = (const float4*)(g_v + nextbase * (PT * DIM));
            for (int i = tid; i < PT * 32; i += 256) {
                int r = i >> 5, c = i & 31;
                cp16(sv_a + (uint32_t)(r * 132 + c * 4) * 4, gv4 + i);
            }
            cp_commit();
        }

        // ---- out accumulate: Wo fragments via one LDG.128 per ks ----
        {
            const float4* wof = ((const float4*)g_woF) + ((size_t)(wid * 8 + h) * 16) * 32 + lane;
            #pragma unroll
            for (int ks = 0; ks < 16; ks++) {
                int k0 = ks * 8;
                float4 av = __ldg(wof + ks * 32);
                uint32_t a[4] = {__float_as_uint(av.x), __float_as_uint(av.y),
                                 __float_as_uint(av.z), __float_as_uint(av.w)};
                #pragma unroll
                for (int nt = 0; nt < 7; nt++) {
                    uint32_t b[2];
                    b[0] = __float_as_uint(att[(nt * 8 + g) * 132 + k0 + t]);
                    b[1] = __float_as_uint(att[(nt * 8 + g) * 132 + k0 + t + 4]);
                    mma_tf32(acc_o[nt], a, b);
                }
            }
        }
        __syncthreads();

        // prefetch next q into sq (= att, reads done)
        if (h < 7) {
            const float4* gq4 = (const float4*)(g_q + nextbase * (PT * DIM));
            for (int i = tid; i < PT * 32; i += 256) {
                int r = i >> 5, c = i & 31;
                cp16(sq_a + (uint32_t)(r * 132 + c * 4) * 4, gq4 + i);
            }
            cp_commit();
        }
    }

    // ---- final store ----
    int wy = w >> 4, wx = w & 15;
    float* dst_n = out + (size_t)n * DIM * PPTS;
    #pragma unroll
    for (int rs = 0; rs < 2; rs++) {
        int o = om0 + g + rs * 8;
        float bias = bo[o];
        float* dst = dst_n + (size_t)o * PPTS;
        #pragma unroll
        for (int nt = 0; nt < 7; nt++) {
            #pragma unroll
            for (int cs = 0; cs < 2; cs++) {
                int tok = nt * 8 + 2 * t + cs;
                if (tok < PT) {
                    int jy = tok / WIN, jx = tok - jy * WIN;
                    int p = (wy * WIN + jy) * CWID + wx * WIN + jx;
                    dst[p] = acc_o[nt][rs * 2 + cs] + bias;
                }
            }
        }
    }
}

// ---------------- launch ----------------
extern "C" void kernel_launch(void* const* d_in, const int* in_sizes, int n_in,
                              void* d_out, int out_size) {
    const float* x   = (const float*)d_in[0];
    const float* Wq  = (const float*)d_in[1];
    const float* bq  = (const float*)d_in[2];
    const float* Wk  = (const float*)d_in[3];
    const float* bk  = (const float*)d_in[4];
    const float* Wv  = (const float*)d_in[5];
    const float* bv  = (const float*)d_in[6];
    const float* Wo  = (const float*)d_in[7];
    const float* bo  = (const float*)d_in[8];
    const float* pos = (const float*)d_in[9];
    float* out = (float*)d_out;

    wo_frag_prep<<<512, 256>>>(Wo);
    {
        dim3 gw(128, 3);
        w_prep<<<gw, 256>>>(Wq, Wk, Wv);
    }
    x_prep<<<6272, 256>>>(x);

    {
        static int attr_set = 0;
        if (!attr_set) {
            cudaFuncSetAttribute(qkv_kernel, cudaFuncAttributeMaxDynamicSharedMemorySize,
                                 Q_SM_FLOATS * (int)sizeof(float));
            cudaFuncSetAttribute(attn_out_kernel, cudaFuncAttributeMaxDynamicSharedMemorySize,
                                 SM_FLOATS * (int)sizeof(float));
            attr_set = 1;
        }
    }
    {
        dim3 grid(PPTS / 256, HEADS, 12);
        qkv_kernel<<<grid, 128, Q_SM_FLOATS * sizeof(float)>>>(bq, bk, bv);
    }
    attn_out_kernel<<<NB * WN, 256, SM_FLOATS * sizeof(float)>>>(pos, bo, out);
}

// round 13
// speedup vs baseline: 1.5211x; 1.3302x over previous
#include <cuda_runtime.h>
#include <cuda_fp16.h>
#include <cstdint>

// ---------------- problem constants ----------------
#define NB    4
#define DIM   128
#define HEADS 8
#define PPTS  12544
#define CWID  112
#define WIN   7
#define NWX   16
#define WN    256
#define PT    49

// q,k: half [n][h][win][tok=49][d=128]; v: float (tf32-rounded), same layout
__device__ __half g_q[(size_t)NB * HEADS * WN * PT * DIM];
__device__ __half g_k[(size_t)NB * HEADS * WN * PT * DIM];
__device__ float  g_v[(size_t)NB * HEADS * WN * PT * DIM];
__device__ uint4  g_woF16[8 * 8 * 8 * 32];                  // Wo fp16 fragment-major [wd][h][ks][lane]
__device__ __half g_wH[(size_t)3 * HEADS * DIM * DIM];      // Wq/Wk/Wv fp16, row-major [o][k]
__device__ __half g_xTH[(size_t)NB * PPTS * DIM];           // x transposed [n][p][k], fp16

__device__ __forceinline__ float tf32f(float x) {
    uint32_t u;
    asm("cvt.rna.tf32.f32 %0, %1;" : "=r"(u) : "f"(x));
    return __uint_as_float(u);
}

__device__ __forceinline__ void mma_f16(float c[4], const uint32_t a[4], const uint32_t b[2]) {
    asm volatile(
        "mma.sync.aligned.m16n8k16.row.col.f32.f16.f16.f32 "
        "{%0,%1,%2,%3}, {%4,%5,%6,%7}, {%8,%9}, {%0,%1,%2,%3};\n"
        : "+f"(c[0]), "+f"(c[1]), "+f"(c[2]), "+f"(c[3])
        : "r"(a[0]), "r"(a[1]), "r"(a[2]), "r"(a[3]), "r"(b[0]), "r"(b[1]));
}

__device__ __forceinline__ void mma_tf32(float c[4], const uint32_t a[4], const uint32_t b[2]) {
    asm volatile(
        "mma.sync.aligned.m16n8k8.row.col.f32.tf32.tf32.f32 "
        "{%0,%1,%2,%3}, {%4,%5,%6,%7}, {%8,%9}, {%0,%1,%2,%3};\n"
        : "+f"(c[0]), "+f"(c[1]), "+f"(c[2]), "+f"(c[3])
        : "r"(a[0]), "r"(a[1]), "r"(a[2]), "r"(a[3]), "r"(b[0]), "r"(b[1]));
}

__device__ __forceinline__ void cp16(uint32_t smem_addr, const void* gptr) {
    asm volatile("cp.async.cg.shared.global [%0], [%1], 16;" :: "r"(smem_addr), "l"(gptr));
}
__device__ __forceinline__ void cp_commit() {
    asm volatile("cp.async.commit_group;");
}

__device__ __forceinline__ uint32_t pack_h2(float a, float b) {
    __half2 h = __floats2half2_rn(a, b);
    return *(uint32_t*)&h;
}

// ---------------- prep kernels ----------------
// Wo -> fp16 fragment-major: uint4 {a0,a1,a2,a3} per (wd,h,ks,lane), m16n8k16 A layout
__global__ void wo_prep16(const float* __restrict__ Wo) {
    int idx = blockIdx.x * 256 + threadIdx.x;    // 16384 total
    int lane = idx & 31;
    int ks   = (idx >> 5) & 7;
    int h    = (idx >> 8) & 7;
    int wd   = idx >> 11;
    int g = lane >> 2, t = lane & 3;
    const float* W1 = Wo + (size_t)(wd * 16 + g) * 1024;
    const float* W2 = Wo + (size_t)(wd * 16 + g + 8) * 1024;
    int c = h * 128 + ks * 16 + 2 * t;
    uint4 v;
    v.x = pack_h2(W1[c], W1[c + 1]);
    v.y = pack_h2(W2[c], W2[c + 1]);
    v.z = pack_h2(W1[c + 8], W1[c + 9]);
    v.w = pack_h2(W2[c + 8], W2[c + 9]);
    g_woF16[idx] = v;
}
__global__ void w_prep16(const float* __restrict__ Wq, const float* __restrict__ Wk,
                         const float* __restrict__ Wv) {
    int i = blockIdx.x * 256 + threadIdx.x;      // 32768 float4 per matrix
    const float* src = (blockIdx.y == 0) ? Wq : (blockIdx.y == 1) ? Wk : Wv;
    float4 v = ((const float4*)src)[i];
    uint2 o;
    o.x = pack_h2(v.x, v.y);
    o.y = pack_h2(v.z, v.w);
    ((uint2*)g_wH)[(size_t)blockIdx.y * 32768 + i] = o;
}
// x [n][k][p] -> g_xTH [n][p][k] fp16
__global__ void xTH_prep(const float* __restrict__ x) {
    __shared__ float tile[32][33];
    int p0 = blockIdx.x * 32, k0 = blockIdx.y * 32, n = blockIdx.z;
    int tx = threadIdx.x & 31, ty = threadIdx.x >> 5;   // 256 threads
    const float* xs = x + (size_t)n * DIM * PPTS;
    #pragma unroll
    for (int r = 0; r < 4; r++)
        tile[ty + r * 8][tx] = xs[(size_t)(k0 + ty + r * 8) * PPTS + p0 + tx];
    __syncthreads();
    int lane = tx, wid = ty;
    #pragma unroll
    for (int rr = 0; rr < 4; rr++) {
        int pr = wid * 4 + rr;
        float val = tile[lane][pr];
        g_xTH[((size_t)n * PPTS + p0 + pr) * DIM + k0 + lane] = __float2half(val);
    }
}

// ---------------- Kernel A: QKV projection, fp16 mma ----------------
// block = (ptile-pair, h, which*4+n); 128 threads, warp tile m64 x n64.
// smem bytes: A half[128][136] @0 (34816); B half[2][128][136] @34816
#define QKV_SMEM (34816 * 3)

__global__ __launch_bounds__(128, 2)
void qkv_kernel(const float* __restrict__ bq, const float* __restrict__ bk,
                const float* __restrict__ bv) {
    extern __shared__ char qsmc[];
    __half* As = (__half*)qsmc;                       // [o][136]
    __half* Bs = (__half*)(qsmc + 34816);             // [2][p][136]

    int z = blockIdx.z;
    int n = z & 3;
    int which = z >> 2;
    const float* bvec = (which == 0) ? bq : (which == 1) ? bk : bv;
    int h = blockIdx.y;
    int p_base = blockIdx.x * 256;
    const __half* Wsrc = g_wH + (size_t)which * 131072 + (size_t)h * 16384;
    const __half* xn = g_xTH + (size_t)n * PPTS * DIM;

    int tid = threadIdx.x, lane = tid & 31, wid = tid >> 5;   // 4 warps
    int g = lane >> 2, t = lane & 3;
    int m0w = (wid >> 1) * 64, n0w = (wid & 1) * 64;

    uint32_t As_a = (uint32_t)__cvta_generic_to_shared(As);
    uint32_t Bs_a = (uint32_t)__cvta_generic_to_shared(Bs);

    // A copy (2048 chunks) + B tile 0 (2048 chunks)
    #pragma unroll
    for (int r = 0; r < 16; r++) {
        int i = tid + r * 128;
        int row = i >> 4, c = i & 15;
        cp16(As_a + (uint32_t)(row * 272 + c * 16), Wsrc + (size_t)row * 128 + c * 8);
    }
    #pragma unroll
    for (int r = 0; r < 16; r++) {
        int i = tid + r * 128;
        int prow = i >> 4, c = i & 15;
        cp16(Bs_a + (uint32_t)(prow * 272 + c * 16),
             xn + ((size_t)p_base + prow) * DIM + c * 8);
    }
    cp_commit();

    // prefetch B tile 1
    #pragma unroll
    for (int r = 0; r < 16; r++) {
        int i = tid + r * 128;
        int prow = i >> 4, c = i & 15;
        cp16(Bs_a + (uint32_t)(34816 + prow * 272 + c * 16),
             xn + ((size_t)p_base + 128 + prow) * DIM + c * 8);
    }
    cp_commit();

    size_t headbase = ((size_t)n * HEADS + h) * WN;
    float biasr[4][2];
    #pragma unroll
    for (int mf = 0; mf < 4; mf++)
        #pragma unroll
        for (int rs = 0; rs < 2; rs++)
            biasr[mf][rs] = bvec[h * 128 + m0w + mf * 16 + rs * 8 + g];

    #pragma unroll
    for (int pt = 0; pt < 2; pt++) {
        if (pt == 0) asm volatile("cp.async.wait_group 1;");
        else         asm volatile("cp.async.wait_group 0;");
        __syncthreads();

        const __half* Bst = Bs + pt * (128 * 136);
        float acc[4][8][4] = {};

        #pragma unroll
        for (int ks = 0; ks < 8; ks++) {
            uint32_t af[4][4], bf[8][2];
            #pragma unroll
            for (int mf = 0; mf < 4; mf++) {
                const __half* r1 = As + (m0w + mf * 16 + g) * 136 + ks * 16 + 2 * t;
                const __half* r2 = r1 + 8 * 136;
                af[mf][0] = *(const uint32_t*)r1;
                af[mf][1] = *(const uint32_t*)r2;
                af[mf][2] = *(const uint32_t*)(r1 + 8);
                af[mf][3] = *(const uint32_t*)(r2 + 8);
            }
            #pragma unroll
            for (int nf = 0; nf < 8; nf++) {
                const __half* br = Bst + (n0w + nf * 8 + g) * 136 + ks * 16 + 2 * t;
                bf[nf][0] = *(const uint32_t*)br;
                bf[nf][1] = *(const uint32_t*)(br + 8);
            }
            #pragma unroll
            for (int mf = 0; mf < 4; mf++)
                #pragma unroll
                for (int nf = 0; nf < 8; nf++)
                    mma_f16(acc[mf][nf], af[mf], bf[nf]);
        }

        // epilogue (overlaps nothing critical; warp-local)
        int pb = p_base + pt * 128;
        #pragma unroll
        for (int nf = 0; nf < 8; nf++) {
            #pragma unroll
            for (int cs = 0; cs < 2; cs++) {
                int p = pb + n0w + nf * 8 + 2 * t + cs;
                int pr = p / CWID, pc = p - pr * CWID;
                int win = (pr / WIN) * NWX + (pc / WIN);
                int tok = (pr % WIN) * WIN + (pc % WIN);
                size_t off = ((headbase + win) * PT + tok) * DIM;
                if (which < 2) {
                    __half* base = (which == 0 ? g_q : g_k) + off;
                    #pragma unroll
                    for (int mf = 0; mf < 4; mf++)
                        #pragma unroll
                        for (int rs = 0; rs < 2; rs++) {
                            int d = m0w + mf * 16 + rs * 8 + g;
                            base[d] = __float2half(acc[mf][nf][rs * 2 + cs] + biasr[mf][rs]);
                        }
                } else {
                    float* base = g_v + off;
                    #pragma unroll
                    for (int mf = 0; mf < 4; mf++)
                        #pragma unroll
                        for (int rs = 0; rs < 2; rs++) {
                            int d = m0w + mf * 16 + rs * 8 + g;
                            base[d] = tf32f(acc[mf][nf][rs * 2 + cs] + biasr[mf][rs]);
                        }
                }
            }
        }
        if (pt == 0) __syncthreads();   // all warps done with B0 region? (B1 separate; sync for As reuse safety not needed; keep for ordering)
    }
}

// ---------------- Kernel B: fused attention + output projection ----------------
// smem byte offsets:
//   sq/att half[64][136] @0        (17408)
//   sk     half[56][136] @17408    (15232)
//   sv     float[56][132] @32640   (29568)
//   S      float[64][60]  @62208   (15360)
//   sball  float[8][176]  @77568   (5632)
#define AT_SQ   0
#define AT_SK   17408
#define AT_SV   32640
#define AT_S    62208
#define AT_SB   77568
#define AT_SMEM 83200

__global__ __launch_bounds__(256, 2)
void attn_out_kernel(const float* __restrict__ pos_code,
                     const float* __restrict__ bo,
                     float* __restrict__ out) {
    extern __shared__ char smc[];
    __half* sq   = (__half*)(smc + AT_SQ);
    __half* sk   = (__half*)(smc + AT_SK);
    float*  sv   = (float*)(smc + AT_SV);
    __half* att  = (__half*)(smc + AT_SQ);     // alias: q dead after QK
    float*  S    = (float*)(smc + AT_S);
    float*  sball= (float*)(smc + AT_SB);

    int bid = blockIdx.x;
    int w = bid & 255;
    int n = bid >> 8;
    int tid = threadIdx.x, lane = tid & 31, wid = tid >> 5;
    int g = lane >> 2, t = lane & 3;
    int m0 = (wid >> 1) * 16;         // PV j-tile
    int half_ = wid & 1;
    int om0 = wid * 16;               // out o-tile

    uint32_t sq_a = (uint32_t)__cvta_generic_to_shared(sq);
    uint32_t sk_a = (uint32_t)__cvta_generic_to_shared(sk);
    uint32_t sv_a = (uint32_t)__cvta_generic_to_shared(sv);

    size_t winbase = ((size_t)n * HEADS) * WN + w;

    // zero sv pad rows, sq garbage rows (NaN safety), load all bias tables
    for (int i = tid; i < 7 * 132; i += 256) sv[49 * 132 + i] = 0.f;
    for (int i = tid; i < 15 * 68; i += 256) ((uint32_t*)(sq + 49 * 136))[i] = 0u;
    for (int j = tid; j < 169 * HEADS; j += 256) {
        int hh = j & 7, ii = j >> 3;
        sball[hh * 176 + ii] = pos_code[j];
    }

    // QK row/bias precompute
    int ib[14];
    #pragma unroll
    for (int nt = 0; nt < 7; nt++) {
        #pragma unroll
        for (int cs = 0; cs < 2; cs++) {
            int i = nt * 8 + 2 * t + cs;
            int yi = i / WIN, xi = i - yi * WIN;
            ib[nt * 2 + cs] = (i < PT) ? (yi + 13 * xi) : -1;
        }
    }
    int qj1 = wid * 16 + g, qj2 = qj1 + 8;
    int off1, off2;
    {
        int y1 = qj1 / WIN, x1 = qj1 - y1 * WIN;
        int y2 = qj2 / WIN, x2 = qj2 - y2 * WIN;
        off1 = (WIN - 1 - y1) + 13 * (WIN - 1 - x1);
        off2 = (WIN - 1 - y2) + 13 * (WIN - 1 - x2);
    }

    // head 0 prefetch: q,k half tiles (784 chunks), v float tile (1568 chunks)
    {
        const __half* gq = g_q + winbase * (PT * DIM);
        const __half* gk = g_k + winbase * (PT * DIM);
        const float4* gv4 = (const float4*)(g_v + winbase * (PT * DIM));
        for (int i = tid; i < 784; i += 256) {
            int r = i >> 4, c = i & 15;
            cp16(sq_a + (uint32_t)(r * 272 + c * 16), gq + r * 128 + c * 8);
            cp16(sk_a + (uint32_t)(r * 272 + c * 16), gk + r * 128 + c * 8);
        }
        for (int i = tid; i < PT * 32; i += 256) {
            int r = i >> 5, c = i & 31;
            cp16(sv_a + (uint32_t)(r * 132 + c * 4) * 4, gv4 + i);
        }
        cp_commit();
    }

    float acc_o[7][4] = {};
    const float scale = 0.08838834764831845f;

    for (int h = 0; h < 8; h++) {
        asm volatile("cp.async.wait_group 0;");
        __syncthreads();

        const float* sb = sball + h * 176;
        size_t nextbase = winbase + (size_t)(h + 1) * WN;

        // ---- fused QK (fp16, 8 k-steps) + softmax: warps 0-3 ----
        if (wid < 4) {
            float acc[7][4] = {};
            #pragma unroll
            for (int ks = 0; ks < 8; ks++) {
                uint32_t a[4];
                const __half* r1 = sq + qj1 * 136 + ks * 16 + 2 * t;
                const __half* r2 = sq + qj2 * 136 + ks * 16 + 2 * t;
                a[0] = *(const uint32_t*)r1;
                a[1] = *(const uint32_t*)r2;
                a[2] = *(const uint32_t*)(r1 + 8);
                a[3] = *(const uint32_t*)(r2 + 8);
                #pragma unroll
                for (int nt = 0; nt < 7; nt++) {
                    const __half* br = sk + (nt * 8 + g) * 136 + ks * 16 + 2 * t;
                    uint32_t b[2];
                    b[0] = *(const uint32_t*)br;
                    b[1] = *(const uint32_t*)(br + 8);
                    mma_f16(acc[nt], a, b);
                }
            }
            #pragma unroll
            for (int nt = 0; nt < 7; nt++) {
                #pragma unroll
                for (int cs = 0; cs < 2; cs++) {
                    int bi = ib[nt * 2 + cs];
                    if (bi >= 0) {
                        acc[nt][cs]     = acc[nt][cs]     * scale + sb[bi + off1];
                        acc[nt][2 + cs] = acc[nt][2 + cs] * scale + sb[bi + off2];
                    } else {
                        acc[nt][cs] = -1e30f;
                        acc[nt][2 + cs] = -1e30f;
                    }
                }
            }
            float m1 = -1e30f, m2 = -1e30f;
            #pragma unroll
            for (int k = 0; k < 7; k++) {
                m1 = fmaxf(m1, fmaxf(acc[k][0], acc[k][1]));
                m2 = fmaxf(m2, fmaxf(acc[k][2], acc[k][3]));
            }
            m1 = fmaxf(m1, __shfl_xor_sync(0xffffffffu, m1, 1));
            m1 = fmaxf(m1, __shfl_xor_sync(0xffffffffu, m1, 2));
            m2 = fmaxf(m2, __shfl_xor_sync(0xffffffffu, m2, 1));
            m2 = fmaxf(m2, __shfl_xor_sync(0xffffffffu, m2, 2));
            float s1 = 0.f, s2 = 0.f;
            #pragma unroll
            for (int k = 0; k < 7; k++) {
                acc[k][0] = __expf(acc[k][0] - m1); s1 += acc[k][0];
                acc[k][1] = __expf(acc[k][1] - m1); s1 += acc[k][1];
                acc[k][2] = __expf(acc[k][2] - m2); s2 += acc[k][2];
                acc[k][3] = __expf(acc[k][3] - m2); s2 += acc[k][3];
            }
            s1 += __shfl_xor_sync(0xffffffffu, s1, 1);
            s1 += __shfl_xor_sync(0xffffffffu, s1, 2);
            s2 += __shfl_xor_sync(0xffffffffu, s2, 1);
            s2 += __shfl_xor_sync(0xffffffffu, s2, 2);
            float inv1 = 1.f / s1, inv2 = 1.f / s2;
            #pragma unroll
            for (int nt = 0; nt < 7; nt++) {
                int n0 = nt * 8;
                S[qj1 * 60 + n0 + 2 * t]     = tf32f(acc[nt][0] * inv1);
                S[qj1 * 60 + n0 + 2 * t + 1] = tf32f(acc[nt][1] * inv1);
                S[qj2 * 60 + n0 + 2 * t]     = tf32f(acc[nt][2] * inv2);
                S[qj2 * 60 + n0 + 2 * t + 1] = tf32f(acc[nt][3] * inv2);
            }
        }
        __syncthreads();

        // prefetch next k (sk free)
        if (h < 7) {
            const __half* gk = g_k + nextbase * (PT * DIM);
            for (int i = tid; i < 784; i += 256) {
                int r = i >> 4, c = i & 15;
                cp16(sk_a + (uint32_t)(r * 272 + c * 16), gk + r * 128 + c * 8);
            }
            cp_commit();
        }

        // ---- PV (tf32, k=56): att[j][d] = P @ V ----
        {
            float acc[8][4] = {};
            #pragma unroll
            for (int ks = 0; ks < 7; ks++) {
                int k0 = ks * 8;
                uint32_t a[4];
                a[0] = __float_as_uint(S[(m0 + g) * 60 + k0 + t]);
                a[1] = __float_as_uint(S[(m0 + g + 8) * 60 + k0 + t]);
                a[2] = __float_as_uint(S[(m0 + g) * 60 + k0 + t + 4]);
                a[3] = __float_as_uint(S[(m0 + g + 8) * 60 + k0 + t + 4]);
                #pragma unroll
                for (int nt = 0; nt < 8; nt++) {
                    int n0 = (half_ * 8 + nt) * 8;
                    uint32_t b[2];
                    b[0] = __float_as_uint(sv[(k0 + t) * 132 + n0 + g]);
                    b[1] = __float_as_uint(sv[(k0 + t + 4) * 132 + n0 + g]);
                    mma_tf32(acc[nt], a, b);
                }
            }
            #pragma unroll
            for (int nt = 0; nt < 8; nt++) {
                int d0 = (half_ * 8 + nt) * 8 + 2 * t;
                *(__half2*)&att[(m0 + g) * 136 + d0]     = __floats2half2_rn(acc[nt][0], acc[nt][1]);
                *(__half2*)&att[(m0 + g + 8) * 136 + d0] = __floats2half2_rn(acc[nt][2], acc[nt][3]);
            }
        }
        __syncthreads();

        // prefetch next v (sv free)
        if (h < 7) {
            const float4* gv4 = (const float4*)(g_v + nextbase * (PT * DIM));
            for (int i = tid; i < PT * 32; i += 256) {
                int r = i >> 5, c = i & 31;
                cp16(sv_a + (uint32_t)(r * 132 + c * 4) * 4, gv4 + i);
            }
            cp_commit();
        }

        // ---- out accumulate (fp16, 8 k-steps), Wo via one LDG.128/ks ----
        {
            const uint4* wof = g_woF16 + ((size_t)(wid * 8 + h) * 8) * 32 + lane;
            #pragma unroll
            for (int ks = 0; ks < 8; ks++) {
                uint4 av = __ldg(wof + ks * 32);
                uint32_t a[4] = {av.x, av.y, av.z, av.w};
                #pragma unroll
                for (int nt = 0; nt < 7; nt++) {
                    const __half* br = att + (nt * 8 + g) * 136 + ks * 16 + 2 * t;
                    uint32_t b[2];
                    b[0] = *(const uint32_t*)br;
                    b[1] = *(const uint32_t*)(br + 8);
                    mma_f16(acc_o[nt], a, b);
                }
            }
        }
        __syncthreads();

        // prefetch next q into sq (= att, reads done)
        if (h < 7) {
            const __half* gq = g_q + nextbase * (PT * DIM);
            for (int i = tid; i < 784; i += 256) {
                int r = i >> 4, c = i & 15;
                cp16(sq_a + (uint32_t)(r * 272 + c * 16), gq + r * 128 + c * 8);
            }
            cp_commit();
        }
    }

    // ---- final store ----
    int wy = w >> 4, wx = w & 15;
    float* dst_n = out + (size_t)n * DIM * PPTS;
    #pragma unroll
    for (int rs = 0; rs < 2; rs++) {
        int o = om0 + g + rs * 8;
        float bias = bo[o];
        float* dst = dst_n + (size_t)o * PPTS;
        #pragma unroll
        for (int nt = 0; nt < 7; nt++) {
            #pragma unroll
            for (int cs = 0; cs < 2; cs++) {
                int tok = nt * 8 + 2 * t + cs;
                if (tok < PT) {
                    int jy = tok / WIN, jx = tok - jy * WIN;
                    int p = (wy * WIN + jy) * CWID + wx * WIN + jx;
                    dst[p] = acc_o[nt][rs * 2 + cs] + bias;
                }
            }
        }
    }
}

// ---------------- launch ----------------
extern "C" void kernel_launch(void* const* d_in, const int* in_sizes, int n_in,
                              void* d_out, int out_size) {
    const float* x   = (const float*)d_in[0];
    const float* Wq  = (const float*)d_in[1];
    const float* bq  = (const float*)d_in[2];
    const float* Wk  = (const float*)d_in[3];
    const float* bk  = (const float*)d_in[4];
    const float* Wv  = (const float*)d_in[5];
    const float* bv  = (const float*)d_in[6];
    const float* Wo  = (const float*)d_in[7];
    const float* bo  = (const float*)d_in[8];
    const float* pos = (const float*)d_in[9];
    float* out = (float*)d_out;

    wo_prep16<<<64, 256>>>(Wo);
    {
        dim3 gw(128, 3);
        w_prep16<<<gw, 256>>>(Wq, Wk, Wv);
    }
    {
        dim3 gx(PPTS / 32, DIM / 32, NB);     // (392, 4, 4)
        xTH_prep<<<gx, 256>>>(x);
    }

    {
        static int attr_set = 0;
        if (!attr_set) {
            cudaFuncSetAttribute(qkv_kernel, cudaFuncAttributeMaxDynamicSharedMemorySize, QKV_SMEM);
            cudaFuncSetAttribute(attn_out_kernel, cudaFuncAttributeMaxDynamicSharedMemorySize, AT_SMEM);
            attr_set = 1;
        }
    }
    {
        dim3 grid(PPTS / 256, HEADS, 12);     // (49, 8, 12)
        qkv_kernel<<<grid, 128, QKV_SMEM>>>(bq, bk, bv);
    }
    attn_out_kernel<<<NB * WN, 256, AT_SMEM>>>(pos, bo, out);
}

// round 15
// speedup vs baseline: 1.5293x; 1.0054x over previous
#include <cuda_runtime.h>
#include <cuda_fp16.h>
#include <cstdint>

// ---------------- problem constants ----------------
#define NB    4
#define DIM   128
#define HEADS 8
#define PPTS  12544
#define CWID  112
#define WIN   7
#define NWX   16
#define WN    256
#define PT    49

// q,k,v: half [n][h][win][tok=49][d=128]
__device__ __half g_q[(size_t)NB * HEADS * WN * PT * DIM];
__device__ __half g_k[(size_t)NB * HEADS * WN * PT * DIM];
__device__ __half g_v[(size_t)NB * HEADS * WN * PT * DIM];
__device__ uint4  g_woF16[8 * 8 * 8 * 32];                  // Wo fp16 fragment-major
__device__ __half g_wH[(size_t)3 * HEADS * DIM * DIM];      // Wq/Wk/Wv fp16 [o][k]
__device__ __half g_xTH[(size_t)NB * PPTS * DIM];           // x transposed [n][p][k] fp16

__device__ __forceinline__ void mma_f16(float c[4], const uint32_t a[4], const uint32_t b[2]) {
    asm volatile(
        "mma.sync.aligned.m16n8k16.row.col.f32.f16.f16.f32 "
        "{%0,%1,%2,%3}, {%4,%5,%6,%7}, {%8,%9}, {%0,%1,%2,%3};\n"
        : "+f"(c[0]), "+f"(c[1]), "+f"(c[2]), "+f"(c[3])
        : "r"(a[0]), "r"(a[1]), "r"(a[2]), "r"(a[3]), "r"(b[0]), "r"(b[1]));
}

__device__ __forceinline__ void ldsm_x2_trans(uint32_t& r0, uint32_t& r1, uint32_t smem_addr) {
    asm volatile("ldmatrix.sync.aligned.m8n8.x2.trans.shared.b16 {%0, %1}, [%2];"
                 : "=r"(r0), "=r"(r1) : "r"(smem_addr));
}

__device__ __forceinline__ void cp16(uint32_t smem_addr, const void* gptr) {
    asm volatile("cp.async.cg.shared.global [%0], [%1], 16;" :: "r"(smem_addr), "l"(gptr));
}
__device__ __forceinline__ void cp_commit() {
    asm volatile("cp.async.commit_group;");
}

__device__ __forceinline__ uint32_t pack_h2(float a, float b) {
    __half2 h = __floats2half2_rn(a, b);
    return *(uint32_t*)&h;
}

// ---------------- prep kernels ----------------
__global__ void wo_prep16(const float* __restrict__ Wo) {
    int idx = blockIdx.x * 256 + threadIdx.x;    // 16384 total
    int lane = idx & 31;
    int ks   = (idx >> 5) & 7;
    int h    = (idx >> 8) & 7;
    int wd   = idx >> 11;
    int g = lane >> 2, t = lane & 3;
    const float* W1 = Wo + (size_t)(wd * 16 + g) * 1024;
    const float* W2 = Wo + (size_t)(wd * 16 + g + 8) * 1024;
    int c = h * 128 + ks * 16 + 2 * t;
    uint4 v;
    v.x = pack_h2(W1[c], W1[c + 1]);
    v.y = pack_h2(W2[c], W2[c + 1]);
    v.z = pack_h2(W1[c + 8], W1[c + 9]);
    v.w = pack_h2(W2[c + 8], W2[c + 9]);
    g_woF16[idx] = v;
}
__global__ void w_prep16(const float* __restrict__ Wq, const float* __restrict__ Wk,
                         const float* __restrict__ Wv) {
    int i = blockIdx.x * 256 + threadIdx.x;      // 32768 float4 per matrix
    const float* src = (blockIdx.y == 0) ? Wq : (blockIdx.y == 1) ? Wk : Wv;
    float4 v = ((const float4*)src)[i];
    uint2 o;
    o.x = pack_h2(v.x, v.y);
    o.y = pack_h2(v.z, v.w);
    ((uint2*)g_wH)[(size_t)blockIdx.y * 32768 + i] = o;
}
__global__ void xTH_prep(const float* __restrict__ x) {
    __shared__ float tile[32][33];
    int p0 = blockIdx.x * 32, k0 = blockIdx.y * 32, n = blockIdx.z;
    int tx = threadIdx.x & 31, ty = threadIdx.x >> 5;
    const float* xs = x + (size_t)n * DIM * PPTS;
    #pragma unroll
    for (int r = 0; r < 4; r++)
        tile[ty + r * 8][tx] = xs[(size_t)(k0 + ty + r * 8) * PPTS + p0 + tx];
    __syncthreads();
    #pragma unroll
    for (int rr = 0; rr < 4; rr++) {
        int pr = ty * 4 + rr;
        g_xTH[((size_t)n * PPTS + p0 + pr) * DIM + k0 + tx] = __float2half(tile[tx][pr]);
    }
}

// ---------------- Kernel A: QKV projection, fp16 mma, 8 warps ----------------
// smem bytes: A half[128][136] @0 (34816); B half[2][128][136] @34816
#define QKV_SMEM (34816 * 3)

__global__ __launch_bounds__(256, 2)
void qkv_kernel(const float* __restrict__ bq, const float* __restrict__ bk,
                const float* __restrict__ bv) {
    extern __shared__ char qsmc[];
    __half* As = (__half*)qsmc;                       // [o][136]
    __half* Bs = (__half*)(qsmc + 34816);             // [2][p][136]

    int z = blockIdx.z;
    int n = z & 3;
    int which = z >> 2;
    const float* bvec = (which == 0) ? bq : (which == 1) ? bk : bv;
    __half* garr = (which == 0) ? g_q : (which == 1) ? g_k : g_v;
    int h = blockIdx.y;
    int p_base = blockIdx.x * 256;
    const __half* Wsrc = g_wH + (size_t)which * 131072 + (size_t)h * 16384;
    const __half* xn = g_xTH + (size_t)n * PPTS * DIM;

    int tid = threadIdx.x, lane = tid & 31, wid = tid >> 5;   // 8 warps
    int g = lane >> 2, t = lane & 3;
    int m0w = (wid >> 2) * 64, n0w = (wid & 3) * 32;

    uint32_t As_a = (uint32_t)__cvta_generic_to_shared(As);
    uint32_t Bs_a = (uint32_t)__cvta_generic_to_shared(Bs);

    // A copy + B tile 0
    #pragma unroll
    for (int r = 0; r < 8; r++) {
        int i = tid + r * 256;
        int row = i >> 4, c = i & 15;
        cp16(As_a + (uint32_t)(row * 272 + c * 16), Wsrc + (size_t)row * 128 + c * 8);
    }
    #pragma unroll
    for (int r = 0; r < 8; r++) {
        int i = tid + r * 256;
        int prow = i >> 4, c = i & 15;
        cp16(Bs_a + (uint32_t)(prow * 272 + c * 16),
             xn + ((size_t)p_base + prow) * DIM + c * 8);
    }
    cp_commit();
    // B tile 1
    #pragma unroll
    for (int r = 0; r < 8; r++) {
        int i = tid + r * 256;
        int prow = i >> 4, c = i & 15;
        cp16(Bs_a + (uint32_t)(34816 + prow * 272 + c * 16),
             xn + ((size_t)p_base + 128 + prow) * DIM + c * 8);
    }
    cp_commit();

    size_t headbase = ((size_t)n * HEADS + h) * WN;
    float biasr[4][2];
    #pragma unroll
    for (int mf = 0; mf < 4; mf++)
        #pragma unroll
        for (int rs = 0; rs < 2; rs++)
            biasr[mf][rs] = bvec[h * 128 + m0w + mf * 16 + rs * 8 + g];

    #pragma unroll
    for (int pt = 0; pt < 2; pt++) {
        if (pt == 0) asm volatile("cp.async.wait_group 1;");
        else         asm volatile("cp.async.wait_group 0;");
        __syncthreads();

        const __half* Bst = Bs + pt * (128 * 136);
        float acc[4][4][4] = {};

        #pragma unroll
        for (int ks = 0; ks < 8; ks++) {
            uint32_t af[4][4], bf[4][2];
            #pragma unroll
            for (int mf = 0; mf < 4; mf++) {
                const __half* r1 = As + (m0w + mf * 16 + g) * 136 + ks * 16 + 2 * t;
                const __half* r2 = r1 + 8 * 136;
                af[mf][0] = *(const uint32_t*)r1;
                af[mf][1] = *(const uint32_t*)r2;
                af[mf][2] = *(const uint32_t*)(r1 + 8);
                af[mf][3] = *(const uint32_t*)(r2 + 8);
            }
            #pragma unroll
            for (int nf = 0; nf < 4; nf++) {
                const __half* br = Bst + (n0w + nf * 8 + g) * 136 + ks * 16 + 2 * t;
                bf[nf][0] = *(const uint32_t*)br;
                bf[nf][1] = *(const uint32_t*)(br + 8);
            }
            #pragma unroll
            for (int mf = 0; mf < 4; mf++)
                #pragma unroll
                for (int nf = 0; nf < 4; nf++)
                    mma_f16(acc[mf][nf], af[mf], bf[nf]);
        }

        int pb = p_base + pt * 128;
        #pragma unroll
        for (int nf = 0; nf < 4; nf++) {
            #pragma unroll
            for (int cs = 0; cs < 2; cs++) {
                int p = pb + n0w + nf * 8 + 2 * t + cs;
                int pr = p / CWID, pc = p - pr * CWID;
                int win = (pr / WIN) * NWX + (pc / WIN);
                int tok = (pr % WIN) * WIN + (pc % WIN);
                __half* base = garr + ((headbase + win) * PT + tok) * DIM;
                #pragma unroll
                for (int mf = 0; mf < 4; mf++)
                    #pragma unroll
                    for (int rs = 0; rs < 2; rs++) {
                        int d = m0w + mf * 16 + rs * 8 + g;
                        base[d] = __float2half(acc[mf][nf][rs * 2 + cs] + biasr[mf][rs]);
                    }
            }
        }
        if (pt == 0) __syncthreads();
    }
}

// ---------------- Kernel B: fused attention + output projection (all fp16 mma) ----------------
// smem byte offsets:
//   sq/att half[64][136] @0        (17408)
//   sk     half[56][136] @17408    (15232)
//   sv     half[64][136] @32640    (17408)  rows 49..63 zeroed once
//   Sh(P)  half[64][68]  @50048    (8704)   cols 56..63 stay zero
//   sball  float[8][176] @58752    (5632)
#define AT_SQ   0
#define AT_SK   17408
#define AT_SV   32640
#define AT_SH   50048
#define AT_SB   58752
#define AT_SMEM 64384

__global__ __launch_bounds__(256, 2)
void attn_out_kernel(const float* __restrict__ pos_code,
                     const float* __restrict__ bo,
                     float* __restrict__ out) {
    extern __shared__ char smc[];
    __half* sq   = (__half*)(smc + AT_SQ);
    __half* sk   = (__half*)(smc + AT_SK);
    __half* sv   = (__half*)(smc + AT_SV);
    __half* att  = (__half*)(smc + AT_SQ);     // alias: q dead after QK
    __half* Sh   = (__half*)(smc + AT_SH);
    float*  sball= (float*)(smc + AT_SB);

    int bid = blockIdx.x;
    int w = bid & 255;
    int n = bid >> 8;
    int tid = threadIdx.x, lane = tid & 31, wid = tid >> 5;
    int g = lane >> 2, t = lane & 3;
    int m0 = (wid >> 1) * 16;         // PV j-tile
    int half_ = wid & 1;
    int om0 = wid * 16;               // out o-tile

    uint32_t sq_a = (uint32_t)__cvta_generic_to_shared(sq);
    uint32_t sk_a = (uint32_t)__cvta_generic_to_shared(sk);
    uint32_t sv_a = (uint32_t)__cvta_generic_to_shared(sv);

    size_t winbase = ((size_t)n * HEADS) * WN + w;

    // one-time zeroing: sv rows 49..63 (15*136 halves), Sh all, sq rows 49..63
    for (int i = tid; i < 1020; i += 256) ((uint32_t*)(sv + 49 * 136))[i] = 0u;
    for (int i = tid; i < 2176; i += 256) ((uint32_t*)Sh)[i] = 0u;
    for (int i = tid; i < 1020; i += 256) ((uint32_t*)(sq + 49 * 136))[i] = 0u;
    for (int j = tid; j < 169 * HEADS; j += 256) {
        int hh = j & 7, ii = j >> 3;
        sball[hh * 176 + ii] = pos_code[j];
    }

    // QK row/bias precompute
    int ib[14];
    #pragma unroll
    for (int nt = 0; nt < 7; nt++) {
        #pragma unroll
        for (int cs = 0; cs < 2; cs++) {
            int i = nt * 8 + 2 * t + cs;
            int yi = i / WIN, xi = i - yi * WIN;
            ib[nt * 2 + cs] = (i < PT) ? (yi + 13 * xi) : -1;
        }
    }
    int qj1 = wid * 16 + g, qj2 = qj1 + 8;
    int off1, off2;
    {
        int y1 = qj1 / WIN, x1 = qj1 - y1 * WIN;
        int y2 = qj2 / WIN, x2 = qj2 - y2 * WIN;
        off1 = (WIN - 1 - y1) + 13 * (WIN - 1 - x1);
        off2 = (WIN - 1 - y2) + 13 * (WIN - 1 - x2);
    }

    // head 0 prefetch: q,k,v half tiles (784 chunks each)
    {
        const __half* gq = g_q + winbase * (PT * DIM);
        const __half* gk = g_k + winbase * (PT * DIM);
        const __half* gv = g_v + winbase * (PT * DIM);
        for (int i = tid; i < 784; i += 256) {
            int r = i >> 4, c = i & 15;
            uint32_t off = (uint32_t)(r * 272 + c * 16);
            cp16(sq_a + off, gq + r * 128 + c * 8);
            cp16(sk_a + off, gk + r * 128 + c * 8);
            cp16(sv_a + off, gv + r * 128 + c * 8);
        }
        cp_commit();
    }

    float acc_o[7][4] = {};
    const float scale = 0.08838834764831845f;

    for (int h = 0; h < 8; h++) {
        asm volatile("cp.async.wait_group 0;");
        __syncthreads();

        const float* sb = sball + h * 176;
        size_t nextbase = winbase + (size_t)(h + 1) * WN;

        // ---- fused QK (fp16) + softmax: warps 0-3 own full rows ----
        if (wid < 4) {
            float acc[7][4] = {};
            #pragma unroll
            for (int ks = 0; ks < 8; ks++) {
                uint32_t a[4];
                const __half* r1 = sq + qj1 * 136 + ks * 16 + 2 * t;
                const __half* r2 = sq + qj2 * 136 + ks * 16 + 2 * t;
                a[0] = *(const uint32_t*)r1;
                a[1] = *(const uint32_t*)r2;
                a[2] = *(const uint32_t*)(r1 + 8);
                a[3] = *(const uint32_t*)(r2 + 8);
                #pragma unroll
                for (int nt = 0; nt < 7; nt++) {
                    const __half* br = sk + (nt * 8 + g) * 136 + ks * 16 + 2 * t;
                    uint32_t b[2];
                    b[0] = *(const uint32_t*)br;
                    b[1] = *(const uint32_t*)(br + 8);
                    mma_f16(acc[nt], a, b);
                }
            }
            #pragma unroll
            for (int nt = 0; nt < 7; nt++) {
                #pragma unroll
                for (int cs = 0; cs < 2; cs++) {
                    int bi = ib[nt * 2 + cs];
                    if (bi >= 0) {
                        acc[nt][cs]     = acc[nt][cs]     * scale + sb[bi + off1];
                        acc[nt][2 + cs] = acc[nt][2 + cs] * scale + sb[bi + off2];
                    } else {
                        acc[nt][cs] = -1e30f;
                        acc[nt][2 + cs] = -1e30f;
                    }
                }
            }
            float m1 = -1e30f, m2 = -1e30f;
            #pragma unroll
            for (int k = 0; k < 7; k++) {
                m1 = fmaxf(m1, fmaxf(acc[k][0], acc[k][1]));
                m2 = fmaxf(m2, fmaxf(acc[k][2], acc[k][3]));
            }
            m1 = fmaxf(m1, __shfl_xor_sync(0xffffffffu, m1, 1));
            m1 = fmaxf(m1, __shfl_xor_sync(0xffffffffu, m1, 2));
            m2 = fmaxf(m2, __shfl_xor_sync(0xffffffffu, m2, 1));
            m2 = fmaxf(m2, __shfl_xor_sync(0xffffffffu, m2, 2));
            float s1 = 0.f, s2 = 0.f;
            #pragma unroll
            for (int k = 0; k < 7; k++) {
                acc[k][0] = __expf(acc[k][0] - m1); s1 += acc[k][0];
                acc[k][1] = __expf(acc[k][1] - m1); s1 += acc[k][1];
                acc[k][2] = __expf(acc[k][2] - m2); s2 += acc[k][2];
                acc[k][3] = __expf(acc[k][3] - m2); s2 += acc[k][3];
            }
            s1 += __shfl_xor_sync(0xffffffffu, s1, 1);
            s1 += __shfl_xor_sync(0xffffffffu, s1, 2);
            s2 += __shfl_xor_sync(0xffffffffu, s2, 1);
            s2 += __shfl_xor_sync(0xffffffffu, s2, 2);
            float inv1 = 1.f / s1, inv2 = 1.f / s2;
            #pragma unroll
            for (int nt = 0; nt < 7; nt++) {
                int n0 = nt * 8;
                *(__half2*)&Sh[qj1 * 68 + n0 + 2 * t] =
                    __floats2half2_rn(acc[nt][0] * inv1, acc[nt][1] * inv1);
                *(__half2*)&Sh[qj2 * 68 + n0 + 2 * t] =
                    __floats2half2_rn(acc[nt][2] * inv2, acc[nt][3] * inv2);
            }
        }
        __syncthreads();

        // prefetch next k
        if (h < 7) {
            const __half* gk = g_k + nextbase * (PT * DIM);
            for (int i = tid; i < 784; i += 256) {
                int r = i >> 4, c = i & 15;
                cp16(sk_a + (uint32_t)(r * 272 + c * 16), gk + r * 128 + c * 8);
            }
            cp_commit();
        }

        // ---- PV (fp16, k=64 padded): att[j][d] = P @ V, B via ldmatrix.trans ----
        {
            float acc[8][4] = {};
            #pragma unroll
            for (int ks = 0; ks < 4; ks++) {
                int k0 = ks * 16;
                uint32_t a[4];
                const __half* pr1 = Sh + (m0 + g) * 68 + k0 + 2 * t;
                const __half* pr2 = Sh + (m0 + g + 8) * 68 + k0 + 2 * t;
                a[0] = *(const uint32_t*)pr1;
                a[1] = *(const uint32_t*)pr2;
                a[2] = *(const uint32_t*)(pr1 + 8);
                a[3] = *(const uint32_t*)(pr2 + 8);
                uint32_t rowaddr = sv_a + (uint32_t)((k0 + (lane & 15)) * 272);
                #pragma unroll
                for (int nt = 0; nt < 8; nt++) {
                    int n0 = (half_ * 8 + nt) * 8;
                    uint32_t b[2];
                    ldsm_x2_trans(b[0], b[1], rowaddr + (uint32_t)(n0 * 2));
                    mma_f16(acc[nt], a, b);
                }
            }
            #pragma unroll
            for (int nt = 0; nt < 8; nt++) {
                int d0 = (half_ * 8 + nt) * 8 + 2 * t;
                *(__half2*)&att[(m0 + g) * 136 + d0]     = __floats2half2_rn(acc[nt][0], acc[nt][1]);
                *(__half2*)&att[(m0 + g + 8) * 136 + d0] = __floats2half2_rn(acc[nt][2], acc[nt][3]);
            }
        }
        __syncthreads();

        // prefetch next v
        if (h < 7) {
            const __half* gv = g_v + nextbase * (PT * DIM);
            for (int i = tid; i < 784; i += 256) {
                int r = i >> 4, c = i & 15;
                cp16(sv_a + (uint32_t)(r * 272 + c * 16), gv + r * 128 + c * 8);
            }
            cp_commit();
        }

        // ---- out accumulate (fp16), Wo via one LDG.128/ks ----
        {
            const uint4* wof = g_woF16 + ((size_t)(wid * 8 + h) * 8) * 32 + lane;
            #pragma unroll
            for (int ks = 0; ks < 8; ks++) {
                uint4 av = __ldg(wof + ks * 32);
                uint32_t a[4] = {av.x, av.y, av.z, av.w};
                #pragma unroll
                for (int nt = 0; nt < 7; nt++) {
                    const __half* br = att + (nt * 8 + g) * 136 + ks * 16 + 2 * t;
                    uint32_t b[2];
                    b[0] = *(const uint32_t*)br;
                    b[1] = *(const uint32_t*)(br + 8);
                    mma_f16(acc_o[nt], a, b);
                }
            }
        }
        __syncthreads();

        // prefetch next q into sq (= att, reads done)
        if (h < 7) {
            const __half* gq = g_q + nextbase * (PT * DIM);
            for (int i = tid; i < 784; i += 256) {
                int r = i >> 4, c = i & 15;
                cp16(sq_a + (uint32_t)(r * 272 + c * 16), gq + r * 128 + c * 8);
            }
            cp_commit();
        }
    }

    // ---- final store ----
    int wy = w >> 4, wx = w & 15;
    float* dst_n = out + (size_t)n * DIM * PPTS;
    #pragma unroll
    for (int rs = 0; rs < 2; rs++) {
        int o = om0 + g + rs * 8;
        float bias = bo[o];
        float* dst = dst_n + (size_t)o * PPTS;
        #pragma unroll
        for (int nt = 0; nt < 7; nt++) {
            #pragma unroll
            for (int cs = 0; cs < 2; cs++) {
                int tok = nt * 8 + 2 * t + cs;
                if (tok < PT) {
                    int jy = tok / WIN, jx = tok - jy * WIN;
                    int p = (wy * WIN + jy) * CWID + wx * WIN + jx;
                    dst[p] = acc_o[nt][rs * 2 + cs] + bias;
                }
            }
        }
    }
}

// ---------------- launch ----------------
extern "C" void kernel_launch(void* const* d_in, const int* in_sizes, int n_in,
                              void* d_out, int out_size) {
    const float* x   = (const float*)d_in[0];
    const float* Wq  = (const float*)d_in[1];
    const float* bq  = (const float*)d_in[2];
    const float* Wk  = (const float*)d_in[3];
    const float* bk  = (const float*)d_in[4];
    const float* Wv  = (const float*)d_in[5];
    const float* bv  = (const float*)d_in[6];
    const float* Wo  = (const float*)d_in[7];
    const float* bo  = (const float*)d_in[8];
    const float* pos = (const float*)d_in[9];
    float* out = (float*)d_out;

    wo_prep16<<<64, 256>>>(Wo);
    {
        dim3 gw(128, 3);
        w_prep16<<<gw, 256>>>(Wq, Wk, Wv);
    }
    {
        dim3 gx(PPTS / 32, DIM / 32, NB);
        xTH_prep<<<gx, 256>>>(x);
    }

    {
        static int attr_set = 0;
        if (!attr_set) {
            cudaFuncSetAttribute(qkv_kernel, cudaFuncAttributeMaxDynamicSharedMemorySize, QKV_SMEM);
            cudaFuncSetAttribute(attn_out_kernel, cudaFuncAttributeMaxDynamicSharedMemorySize, AT_SMEM);
            attr_set = 1;
        }
    }
    {
        dim3 grid(PPTS / 256, HEADS, 12);     // (49, 8, 12)
        qkv_kernel<<<grid, 256, QKV_SMEM>>>(bq, bk, bv);
    }
    attn_out_kernel<<<NB * WN, 256, AT_SMEM>>>(pos, bo, out);
}

// round 16
// speedup vs baseline: 1.5893x; 1.0393x over previous
#include <cuda_runtime.h>
#include <cuda_fp16.h>
#include <cstdint>

// ---------------- problem constants ----------------
#define NB    4
#define DIM   128
#define HEADS 8
#define PPTS  12544
#define CWID  112
#define WIN   7
#define NWX   16
#define WN    256
#define PT    49

// q,k,v: half [n][h][win][tok=49][d=128]
__device__ __half g_q[(size_t)NB * HEADS * WN * PT * DIM];
__device__ __half g_k[(size_t)NB * HEADS * WN * PT * DIM];
__device__ __half g_v[(size_t)NB * HEADS * WN * PT * DIM];
__device__ uint4  g_woF16[8 * 8 * 8 * 32];                  // Wo fp16 fragment-major
__device__ __half g_wH[(size_t)3 * HEADS * DIM * DIM];      // Wq/Wk/Wv fp16 [o][k]
__device__ __half g_xTH[(size_t)NB * PPTS * DIM];           // x transposed [n][p][k] fp16

__device__ __forceinline__ void mma_f16(float c[4], const uint32_t a[4], const uint32_t b[2]) {
    asm volatile(
        "mma.sync.aligned.m16n8k16.row.col.f32.f16.f16.f32 "
        "{%0,%1,%2,%3}, {%4,%5,%6,%7}, {%8,%9}, {%0,%1,%2,%3};\n"
        : "+f"(c[0]), "+f"(c[1]), "+f"(c[2]), "+f"(c[3])
        : "r"(a[0]), "r"(a[1]), "r"(a[2]), "r"(a[3]), "r"(b[0]), "r"(b[1]));
}

__device__ __forceinline__ void ldsm_x2_trans(uint32_t& r0, uint32_t& r1, uint32_t smem_addr) {
    asm volatile("ldmatrix.sync.aligned.m8n8.x2.trans.shared.b16 {%0, %1}, [%2];"
                 : "=r"(r0), "=r"(r1) : "r"(smem_addr));
}

__device__ __forceinline__ void cp16(uint32_t smem_addr, const void* gptr) {
    asm volatile("cp.async.cg.shared.global [%0], [%1], 16;" :: "r"(smem_addr), "l"(gptr));
}
__device__ __forceinline__ void cp_commit() {
    asm volatile("cp.async.commit_group;");
}

__device__ __forceinline__ uint32_t pack_h2(float a, float b) {
    __half2 h = __floats2half2_rn(a, b);
    return *(uint32_t*)&h;
}

// ---------------- prep kernels ----------------
__global__ void wo_prep16(const float* __restrict__ Wo) {
    int idx = blockIdx.x * 256 + threadIdx.x;    // 16384 total
    int lane = idx & 31;
    int ks   = (idx >> 5) & 7;
    int h    = (idx >> 8) & 7;
    int wd   = idx >> 11;
    int g = lane >> 2, t = lane & 3;
    const float* W1 = Wo + (size_t)(wd * 16 + g) * 1024;
    const float* W2 = Wo + (size_t)(wd * 16 + g + 8) * 1024;
    int c = h * 128 + ks * 16 + 2 * t;
    uint4 v;
    v.x = pack_h2(W1[c], W1[c + 1]);
    v.y = pack_h2(W2[c], W2[c + 1]);
    v.z = pack_h2(W1[c + 8], W1[c + 9]);
    v.w = pack_h2(W2[c + 8], W2[c + 9]);
    g_woF16[idx] = v;
}
__global__ void w_prep16(const float* __restrict__ Wq, const float* __restrict__ Wk,
                         const float* __restrict__ Wv) {
    int i = blockIdx.x * 256 + threadIdx.x;      // 32768 float4 per matrix
    const float* src = (blockIdx.y == 0) ? Wq : (blockIdx.y == 1) ? Wk : Wv;
    float4 v = ((const float4*)src)[i];
    uint2 o;
    o.x = pack_h2(v.x, v.y);
    o.y = pack_h2(v.z, v.w);
    ((uint2*)g_wH)[(size_t)blockIdx.y * 32768 + i] = o;
}
__global__ void xTH_prep(const float* __restrict__ x) {
    __shared__ float tile[32][33];
    int p0 = blockIdx.x * 32, k0 = blockIdx.y * 32, n = blockIdx.z;
    int tx = threadIdx.x & 31, ty = threadIdx.x >> 5;
    const float* xs = x + (size_t)n * DIM * PPTS;
    #pragma unroll
    for (int r = 0; r < 4; r++)
        tile[ty + r * 8][tx] = xs[(size_t)(k0 + ty + r * 8) * PPTS + p0 + tx];
    __syncthreads();
    #pragma unroll
    for (int rr = 0; rr < 4; rr++) {
        int pr = ty * 4 + rr;
        g_xTH[((size_t)n * PPTS + p0 + pr) * DIM + k0 + tx] = __float2half(tile[tx][pr]);
    }
}

// ---------------- Kernel A: QKV projection, fp16 mma, 4 warps (R13 config) ----------------
// smem bytes: A half[128][136] @0 (34816); B half[2][128][136] @34816
#define QKV_SMEM (34816 * 3)

__global__ __launch_bounds__(128, 2)
void qkv_kernel(const float* __restrict__ bq, const float* __restrict__ bk,
                const float* __restrict__ bv) {
    extern __shared__ char qsmc[];
    __half* As = (__half*)qsmc;                       // [o][136]
    __half* Bs = (__half*)(qsmc + 34816);             // [2][p][136]

    int z = blockIdx.z;
    int n = z & 3;
    int which = z >> 2;
    const float* bvec = (which == 0) ? bq : (which == 1) ? bk : bv;
    __half* garr = (which == 0) ? g_q : (which == 1) ? g_k : g_v;
    int h = blockIdx.y;
    int p_base = blockIdx.x * 256;
    const __half* Wsrc = g_wH + (size_t)which * 131072 + (size_t)h * 16384;
    const __half* xn = g_xTH + (size_t)n * PPTS * DIM;

    int tid = threadIdx.x, lane = tid & 31, wid = tid >> 5;   // 4 warps
    int g = lane >> 2, t = lane & 3;
    int m0w = (wid >> 1) * 64, n0w = (wid & 1) * 64;

    uint32_t As_a = (uint32_t)__cvta_generic_to_shared(As);
    uint32_t Bs_a = (uint32_t)__cvta_generic_to_shared(Bs);

    // A copy (2048 chunks) + B tile 0 (2048 chunks)
    #pragma unroll
    for (int r = 0; r < 16; r++) {
        int i = tid + r * 128;
        int row = i >> 4, c = i & 15;
        cp16(As_a + (uint32_t)(row * 272 + c * 16), Wsrc + (size_t)row * 128 + c * 8);
    }
    #pragma unroll
    for (int r = 0; r < 16; r++) {
        int i = tid + r * 128;
        int prow = i >> 4, c = i & 15;
        cp16(Bs_a + (uint32_t)(prow * 272 + c * 16),
             xn + ((size_t)p_base + prow) * DIM + c * 8);
    }
    cp_commit();
    // B tile 1
    #pragma unroll
    for (int r = 0; r < 16; r++) {
        int i = tid + r * 128;
        int prow = i >> 4, c = i & 15;
        cp16(Bs_a + (uint32_t)(34816 + prow * 272 + c * 16),
             xn + ((size_t)p_base + 128 + prow) * DIM + c * 8);
    }
    cp_commit();

    size_t headbase = ((size_t)n * HEADS + h) * WN;
    float biasr[4][2];
    #pragma unroll
    for (int mf = 0; mf < 4; mf++)
        #pragma unroll
        for (int rs = 0; rs < 2; rs++)
            biasr[mf][rs] = bvec[h * 128 + m0w + mf * 16 + rs * 8 + g];

    #pragma unroll
    for (int pt = 0; pt < 2; pt++) {
        if (pt == 0) asm volatile("cp.async.wait_group 1;");
        else         asm volatile("cp.async.wait_group 0;");
        __syncthreads();

        const __half* Bst = Bs + pt * (128 * 136);
        float acc[4][8][4] = {};

        #pragma unroll
        for (int ks = 0; ks < 8; ks++) {
            uint32_t af[4][4], bf[8][2];
            #pragma unroll
            for (int mf = 0; mf < 4; mf++) {
                const __half* r1 = As + (m0w + mf * 16 + g) * 136 + ks * 16 + 2 * t;
                const __half* r2 = r1 + 8 * 136;
                af[mf][0] = *(const uint32_t*)r1;
                af[mf][1] = *(const uint32_t*)r2;
                af[mf][2] = *(const uint32_t*)(r1 + 8);
                af[mf][3] = *(const uint32_t*)(r2 + 8);
            }
            #pragma unroll
            for (int nf = 0; nf < 8; nf++) {
                const __half* br = Bst + (n0w + nf * 8 + g) * 136 + ks * 16 + 2 * t;
                bf[nf][0] = *(const uint32_t*)br;
                bf[nf][1] = *(const uint32_t*)(br + 8);
            }
            #pragma unroll
            for (int mf = 0; mf < 4; mf++)
                #pragma unroll
                for (int nf = 0; nf < 8; nf++)
                    mma_f16(acc[mf][nf], af[mf], bf[nf]);
        }

        int pb = p_base + pt * 128;
        #pragma unroll
        for (int nf = 0; nf < 8; nf++) {
            #pragma unroll
            for (int cs = 0; cs < 2; cs++) {
                int p = pb + n0w + nf * 8 + 2 * t + cs;
                int pr = p / CWID, pc = p - pr * CWID;
                int win = (pr / WIN) * NWX + (pc / WIN);
                int tok = (pr % WIN) * WIN + (pc % WIN);
                __half* base = garr + ((headbase + win) * PT + tok) * DIM;
                #pragma unroll
                for (int mf = 0; mf < 4; mf++)
                    #pragma unroll
                    for (int rs = 0; rs < 2; rs++) {
                        int d = m0w + mf * 16 + rs * 8 + g;
                        base[d] = __float2half(acc[mf][nf][rs * 2 + cs] + biasr[mf][rs]);
                    }
            }
        }
        if (pt == 0) __syncthreads();
    }
}

// ---------------- Kernel B: fused attention + output projection (all fp16 mma) ----------------
// smem byte offsets:
//   sq/att half[64][136] @0        (17408)
//   sk     half[56][136] @17408    (15232)
//   sv     half[64][136] @32640    (17408)  rows 49..63 zeroed once
//   Sh(P)  half[64][68]  @50048    (8704)   cols 56..63 stay zero
//   sball  float[8][176] @58752    (5632)
#define AT_SQ   0
#define AT_SK   17408
#define AT_SV   32640
#define AT_SH   50048
#define AT_SB   58752
#define AT_SMEM 64384

__global__ __launch_bounds__(256, 2)
void attn_out_kernel(const float* __restrict__ pos_code,
                     const float* __restrict__ bo,
                     float* __restrict__ out) {
    extern __shared__ char smc[];
    __half* sq   = (__half*)(smc + AT_SQ);
    __half* sk   = (__half*)(smc + AT_SK);
    __half* sv   = (__half*)(smc + AT_SV);
    __half* att  = (__half*)(smc + AT_SQ);     // alias: q dead after QK
    __half* Sh   = (__half*)(smc + AT_SH);
    float*  sball= (float*)(smc + AT_SB);

    int bid = blockIdx.x;
    int w = bid & 255;
    int n = bid >> 8;
    int tid = threadIdx.x, lane = tid & 31, wid = tid >> 5;
    int g = lane >> 2, t = lane & 3;
    int m0 = (wid >> 1) * 16;         // PV j-tile
    int half_ = wid & 1;
    int om0 = wid * 16;               // out o-tile

    uint32_t sq_a = (uint32_t)__cvta_generic_to_shared(sq);
    uint32_t sk_a = (uint32_t)__cvta_generic_to_shared(sk);
    uint32_t sv_a = (uint32_t)__cvta_generic_to_shared(sv);

    size_t winbase = ((size_t)n * HEADS) * WN + w;

    // one-time zeroing: sv rows 49..63, Sh all, sq rows 49..63
    for (int i = tid; i < 1020; i += 256) ((uint32_t*)(sv + 49 * 136))[i] = 0u;
    for (int i = tid; i < 2176; i += 256) ((uint32_t*)Sh)[i] = 0u;
    for (int i = tid; i < 1020; i += 256) ((uint32_t*)(sq + 49 * 136))[i] = 0u;
    for (int j = tid; j < 169 * HEADS; j += 256) {
        int hh = j & 7, ii = j >> 3;
        sball[hh * 176 + ii] = pos_code[j];
    }

    // QK row/bias precompute
    int ib[14];
    #pragma unroll
    for (int nt = 0; nt < 7; nt++) {
        #pragma unroll
        for (int cs = 0; cs < 2; cs++) {
            int i = nt * 8 + 2 * t + cs;
            int yi = i / WIN, xi = i - yi * WIN;
            ib[nt * 2 + cs] = (i < PT) ? (yi + 13 * xi) : -1;
        }
    }
    int qj1 = wid * 16 + g, qj2 = qj1 + 8;
    int off1, off2;
    {
        int y1 = qj1 / WIN, x1 = qj1 - y1 * WIN;
        int y2 = qj2 / WIN, x2 = qj2 - y2 * WIN;
        off1 = (WIN - 1 - y1) + 13 * (WIN - 1 - x1);
        off2 = (WIN - 1 - y2) + 13 * (WIN - 1 - x2);
    }

    // head 0 prefetch: q,k,v half tiles (784 chunks each)
    {
        const __half* gq = g_q + winbase * (PT * DIM);
        const __half* gk = g_k + winbase * (PT * DIM);
        const __half* gv = g_v + winbase * (PT * DIM);
        for (int i = tid; i < 784; i += 256) {
            int r = i >> 4, c = i & 15;
            uint32_t off = (uint32_t)(r * 272 + c * 16);
            cp16(sq_a + off, gq + r * 128 + c * 8);
            cp16(sk_a + off, gk + r * 128 + c * 8);
            cp16(sv_a + off, gv + r * 128 + c * 8);
        }
        cp_commit();
    }

    float acc_o[7][4] = {};
    const float scale = 0.08838834764831845f;

    for (int h = 0; h < 8; h++) {
        asm volatile("cp.async.wait_group 0;");
        __syncthreads();

        const float* sb = sball + h * 176;
        size_t nextbase = winbase + (size_t)(h + 1) * WN;

        // ---- fused QK (fp16) + softmax: warps 0-3 own full rows ----
        if (wid < 4) {
            float acc[7][4] = {};
            #pragma unroll
            for (int ks = 0; ks < 8; ks++) {
                uint32_t a[4];
                const __half* r1 = sq + qj1 * 136 + ks * 16 + 2 * t;
                const __half* r2 = sq + qj2 * 136 + ks * 16 + 2 * t;
                a[0] = *(const uint32_t*)r1;
                a[1] = *(const uint32_t*)r2;
                a[2] = *(const uint32_t*)(r1 + 8);
                a[3] = *(const uint32_t*)(r2 + 8);
                #pragma unroll
                for (int nt = 0; nt < 7; nt++) {
                    const __half* br = sk + (nt * 8 + g) * 136 + ks * 16 + 2 * t;
                    uint32_t b[2];
                    b[0] = *(const uint32_t*)br;
                    b[1] = *(const uint32_t*)(br + 8);
                    mma_f16(acc[nt], a, b);
                }
            }
            #pragma unroll
            for (int nt = 0; nt < 7; nt++) {
                #pragma unroll
                for (int cs = 0; cs < 2; cs++) {
                    int bi = ib[nt * 2 + cs];
                    if (bi >= 0) {
                        acc[nt][cs]     = acc[nt][cs]     * scale + sb[bi + off1];
                        acc[nt][2 + cs] = acc[nt][2 + cs] * scale + sb[bi + off2];
                    } else {
                        acc[nt][cs] = -1e30f;
                        acc[nt][2 + cs] = -1e30f;
                    }
                }
            }
            float m1 = -1e30f, m2 = -1e30f;
            #pragma unroll
            for (int k = 0; k < 7; k++) {
                m1 = fmaxf(m1, fmaxf(acc[k][0], acc[k][1]));
                m2 = fmaxf(m2, fmaxf(acc[k][2], acc[k][3]));
            }
            m1 = fmaxf(m1, __shfl_xor_sync(0xffffffffu, m1, 1));
            m1 = fmaxf(m1, __shfl_xor_sync(0xffffffffu, m1, 2));
            m2 = fmaxf(m2, __shfl_xor_sync(0xffffffffu, m2, 1));
            m2 = fmaxf(m2, __shfl_xor_sync(0xffffffffu, m2, 2));
            float s1 = 0.f, s2 = 0.f;
            #pragma unroll
            for (int k = 0; k < 7; k++) {
                acc[k][0] = __expf(acc[k][0] - m1); s1 += acc[k][0];
                acc[k][1] = __expf(acc[k][1] - m1); s1 += acc[k][1];
                acc[k][2] = __expf(acc[k][2] - m2); s2 += acc[k][2];
                acc[k][3] = __expf(acc[k][3] - m2); s2 += acc[k][3];
            }
            s1 += __shfl_xor_sync(0xffffffffu, s1, 1);
            s1 += __shfl_xor_sync(0xffffffffu, s1, 2);
            s2 += __shfl_xor_sync(0xffffffffu, s2, 1);
            s2 += __shfl_xor_sync(0xffffffffu, s2, 2);
            float inv1 = 1.f / s1, inv2 = 1.f / s2;
            #pragma unroll
            for (int nt = 0; nt < 7; nt++) {
                int n0 = nt * 8;
                *(__half2*)&Sh[qj1 * 68 + n0 + 2 * t] =
                    __floats2half2_rn(acc[nt][0] * inv1, acc[nt][1] * inv1);
                *(__half2*)&Sh[qj2 * 68 + n0 + 2 * t] =
                    __floats2half2_rn(acc[nt][2] * inv2, acc[nt][3] * inv2);
            }
        }
        __syncthreads();

        // prefetch next k
        if (h < 7) {
            const __half* gk = g_k + nextbase * (PT * DIM);
            for (int i = tid; i < 784; i += 256) {
                int r = i >> 4, c = i & 15;
                cp16(sk_a + (uint32_t)(r * 272 + c * 16), gk + r * 128 + c * 8);
            }
            cp_commit();
        }

        // ---- PV (fp16, k=64 padded): att[j][d] = P @ V, B via ldmatrix.trans ----
        {
            float acc[8][4] = {};
            #pragma unroll
            for (int ks = 0; ks < 4; ks++) {
                int k0 = ks * 16;
                uint32_t a[4];
                const __half* pr1 = Sh + (m0 + g) * 68 + k0 + 2 * t;
                const __half* pr2 = Sh + (m0 + g + 8) * 68 + k0 + 2 * t;
                a[0] = *(const uint32_t*)pr1;
                a[1] = *(const uint32_t*)pr2;
                a[2] = *(const uint32_t*)(pr1 + 8);
                a[3] = *(const uint32_t*)(pr2 + 8);
                uint32_t rowaddr = sv_a + (uint32_t)((k0 + (lane & 15)) * 272);
                #pragma unroll
                for (int nt = 0; nt < 8; nt++) {
                    int n0 = (half_ * 8 + nt) * 8;
                    uint32_t b[2];
                    ldsm_x2_trans(b[0], b[1], rowaddr + (uint32_t)(n0 * 2));
                    mma_f16(acc[nt], a, b);
                }
            }
            #pragma unroll
            for (int nt = 0; nt < 8; nt++) {
                int d0 = (half_ * 8 + nt) * 8 + 2 * t;
                *(__half2*)&att[(m0 + g) * 136 + d0]     = __floats2half2_rn(acc[nt][0], acc[nt][1]);
                *(__half2*)&att[(m0 + g + 8) * 136 + d0] = __floats2half2_rn(acc[nt][2], acc[nt][3]);
            }
        }
        __syncthreads();

        // prefetch next v
        if (h < 7) {
            const __half* gv = g_v + nextbase * (PT * DIM);
            for (int i = tid; i < 784; i += 256) {
                int r = i >> 4, c = i & 15;
                cp16(sv_a + (uint32_t)(r * 272 + c * 16), gv + r * 128 + c * 8);
            }
            cp_commit();
        }

        // ---- out accumulate (fp16), Wo via one LDG.128/ks ----
        {
            const uint4* wof = g_woF16 + ((size_t)(wid * 8 + h) * 8) * 32 + lane;
            #pragma unroll
            for (int ks = 0; ks < 8; ks++) {
                uint4 av = __ldg(wof + ks * 32);
                uint32_t a[4] = {av.x, av.y, av.z, av.w};
                #pragma unroll
                for (int nt = 0; nt < 7; nt++) {
                    const __half* br = att + (nt * 8 + g) * 136 + ks * 16 + 2 * t;
                    uint32_t b[2];
                    b[0] = *(const uint32_t*)br;
                    b[1] = *(const uint32_t*)(br + 8);
                    mma_f16(acc_o[nt], a, b);
                }
            }
        }
        __syncthreads();

        // prefetch next q into sq (= att, reads done)
        if (h < 7) {
            const __half* gq = g_q + nextbase * (PT * DIM);
            for (int i = tid; i < 784; i += 256) {
                int r = i >> 4, c = i & 15;
                cp16(sq_a + (uint32_t)(r * 272 + c * 16), gq + r * 128 + c * 8);
            }
            cp_commit();
        }
    }

    // ---- final store ----
    int wy = w >> 4, wx = w & 15;
    float* dst_n = out + (size_t)n * DIM * PPTS;
    #pragma unroll
    for (int rs = 0; rs < 2; rs++) {
        int o = om0 + g + rs * 8;
        float bias = bo[o];
        float* dst = dst_n + (size_t)o * PPTS;
        #pragma unroll
        for (int nt = 0; nt < 7; nt++) {
            #pragma unroll
            for (int cs = 0; cs < 2; cs++) {
                int tok = nt * 8 + 2 * t + cs;
                if (tok < PT) {
                    int jy = tok / WIN, jx = tok - jy * WIN;
                    int p = (wy * WIN + jy) * CWID + wx * WIN + jx;
                    dst[p] = acc_o[nt][rs * 2 + cs] + bias;
                }
            }
        }
    }
}

// ---------------- launch ----------------
extern "C" void kernel_launch(void* const* d_in, const int* in_sizes, int n_in,
                              void* d_out, int out_size) {
    const float* x   = (const float*)d_in[0];
    const float* Wq  = (const float*)d_in[1];
    const float* bq  = (const float*)d_in[2];
    const float* Wk  = (const float*)d_in[3];
    const float* bk  = (const float*)d_in[4];
    const float* Wv  = (const float*)d_in[5];
    const float* bv  = (const float*)d_in[6];
    const float* Wo  = (const float*)d_in[7];
    const float* bo  = (const float*)d_in[8];
    const float* pos = (const float*)d_in[9];
    float* out = (float*)d_out;

    wo_prep16<<<64, 256>>>(Wo);
    {
        dim3 gw(128, 3);
        w_prep16<<<gw, 256>>>(Wq, Wk, Wv);
    }
    {
        dim3 gx(PPTS / 32, DIM / 32, NB);
        xTH_prep<<<gx, 256>>>(x);
    }

    {
        static int attr_set = 0;
        if (!attr_set) {
            cudaFuncSetAttribute(qkv_kernel, cudaFuncAttributeMaxDynamicSharedMemorySize, QKV_SMEM);
            cudaFuncSetAttribute(attn_out_kernel, cudaFuncAttributeMaxDynamicSharedMemorySize, AT_SMEM);
            attr_set = 1;
        }
    }
    {
        dim3 grid(PPTS / 256, HEADS, 12);     // (49, 8, 12)
        qkv_kernel<<<grid, 128, QKV_SMEM>>>(bq, bk, bv);
    }
    attn_out_kernel<<<NB * WN, 256, AT_SMEM>>>(pos, bo, out);
}